// round 10
// baseline (speedup 1.0000x reference)
#include <cuda_runtime.h>
#include <math.h>
#include <float.h>

// Problem dims
#define T_SEQ 256
#define BATCH 512
#define IND   128
#define H1D   100
#define G1D   400     // 4*H1
#define H2D   128
#define G2D   512     // 4*H2
#define NC    19

typedef unsigned long long u64;

__device__ __forceinline__ void ffma2(u64 &d, u64 a, u64 b) {
    asm("fma.rn.f32x2 %0, %1, %2, %0;" : "+l"(d) : "l"(a), "l"(b));
}
__device__ __forceinline__ u64 pack2(float x, float y) {
    u64 r; asm("mov.b64 %0, {%1, %2};" : "=l"(r) : "f"(x), "f"(y)); return r;
}
__device__ __forceinline__ float2 unpk(u64 v) {
    float2 r; asm("mov.b64 {%0, %1}, %2;" : "=f"(r.x), "=f"(r.y) : "l"(v)); return r;
}
__device__ __forceinline__ float fsig(float a) {
    return __fdividef(1.f, 1.f + __expf(-a));
}

// ---------------- scratch ---------------------------------------------------
__device__ float g_zx1[256u*512u*400u];   // [(t,b)][G1]
__device__ float g_h1 [256u*512u*100u];   // [(t,b)][H1]
__device__ float g_zx2[256u*512u*512u];   // [(t,b)][G2]
__device__ float g_h2 [512u*128u];        // [B][H2]

// ---------------- feedforward GEMM: A-resident n-loop + reg-prefetched B ----
// B tile nt+1 loaded into 8 float4 regs during compute of tile nt; the
// inter-barrier phase is just 8 STS.128. A tile loaded once (vectorized).
#define BM 64
#define BN 64
#define KMAX 128
#define AP 68

__global__ __launch_bounds__(256, 3)
void gemm_ff(const float* __restrict__ A, const float* __restrict__ Bw,
             const float* __restrict__ bias, float* __restrict__ C,
             int M, int N, int K, int mode)
{
    extern __shared__ float sm[];
    float* As = sm;                 // [KMAX][AP]  transposed A tile
    float* Bs = sm + KMAX * AP;     // [KMAX][BN]

    const int tid = threadIdx.x;
    const int m0 = blockIdx.x * BM;
    const int tx = tid & 15, ty = tid >> 4;

    // load A tile once (float4 LDG, scalar scatter STS)
    const int nf4 = K >> 2;                       // K/4 (both 128 and 100 divisible)
    for (int idx = tid; idx < BM * nf4; idx += 256) {
        int mloc = idx / nf4;
        int f = idx - mloc * nf4;
        int m = m0 + mloc;
        size_t arow;
        if (mode) { int t = m >> 9; int b = m & 511; arow = ((size_t)(b * T_SEQ + t)) * IND; }
        else      { arow = (size_t)m * K; }
        float4 v = *reinterpret_cast<const float4*>(&A[arow + 4 * f]);
        As[(4 * f + 0) * AP + mloc] = v.x;
        As[(4 * f + 1) * AP + mloc] = v.y;
        As[(4 * f + 2) * AP + mloc] = v.z;
        As[(4 * f + 3) * AP + mloc] = v.w;
    }

    // prefetch B tile 0 into regs: thread owns 8 float4 (flat = tid*8+i,
    // k = flat/16, n4 = flat%16)
    float4 pb[8];
#pragma unroll
    for (int i = 0; i < 8; i++) {
        int flat = tid * 8 + i;
        int kk = flat >> 4;
        int gn = (flat & 15) * 4;
        if (gn + 3 < N) {
            pb[i] = *reinterpret_cast<const float4*>(&Bw[(size_t)kk * N + gn]);
        } else {
            pb[i].x = (gn + 0 < N) ? Bw[(size_t)kk * N + gn + 0] : 0.f;
            pb[i].y = (gn + 1 < N) ? Bw[(size_t)kk * N + gn + 1] : 0.f;
            pb[i].z = (gn + 2 < N) ? Bw[(size_t)kk * N + gn + 2] : 0.f;
            pb[i].w = (gn + 3 < N) ? Bw[(size_t)kk * N + gn + 3] : 0.f;
        }
    }

    const int ntiles = (N + BN - 1) / BN;
    for (int nt = 0; nt < ntiles; ++nt) {
        const int n0 = nt * BN;
        __syncthreads();                 // prior compute done; A stores visible (nt=0)
        // commit prefetched B to smem
#pragma unroll
        for (int i = 0; i < 8; i++) {
            int flat = tid * 8 + i;
            int kk = flat >> 4;
            int nn = (flat & 15) * 4;
            *reinterpret_cast<float4*>(&Bs[kk * BN + nn]) = pb[i];
        }
        __syncthreads();                 // Bs ready

        // issue next tile's B loads (latency hidden behind compute below)
        if (nt + 1 < ntiles) {
            const int n0n = n0 + BN;
#pragma unroll
            for (int i = 0; i < 8; i++) {
                int flat = tid * 8 + i;
                int kk = flat >> 4;
                int gn = n0n + (flat & 15) * 4;
                if (gn + 3 < N) {
                    pb[i] = *reinterpret_cast<const float4*>(&Bw[(size_t)kk * N + gn]);
                } else {
                    pb[i].x = (gn + 0 < N) ? Bw[(size_t)kk * N + gn + 0] : 0.f;
                    pb[i].y = (gn + 1 < N) ? Bw[(size_t)kk * N + gn + 1] : 0.f;
                    pb[i].z = (gn + 2 < N) ? Bw[(size_t)kk * N + gn + 2] : 0.f;
                    pb[i].w = (gn + 3 < N) ? Bw[(size_t)kk * N + gn + 3] : 0.f;
                }
            }
        }

        u64 acc2[2][4];
#pragma unroll
        for (int i = 0; i < 2; i++)
#pragma unroll
            for (int j = 0; j < 4; j++) acc2[i][j] = 0ull;

#pragma unroll 4
        for (int k = 0; k < K; ++k) {
            ulonglong2 av = *reinterpret_cast<const ulonglong2*>(&As[k * AP + ty * 4]);
            float4 bv = *reinterpret_cast<const float4*>(&Bs[k * BN + tx * 4]);
            u64 b0 = pack2(bv.x, bv.x);
            u64 b1 = pack2(bv.y, bv.y);
            u64 b2 = pack2(bv.z, bv.z);
            u64 b3 = pack2(bv.w, bv.w);
            ffma2(acc2[0][0], av.x, b0); ffma2(acc2[0][1], av.x, b1);
            ffma2(acc2[0][2], av.x, b2); ffma2(acc2[0][3], av.x, b3);
            ffma2(acc2[1][0], av.y, b0); ffma2(acc2[1][1], av.y, b1);
            ffma2(acc2[1][2], av.y, b2); ffma2(acc2[1][3], av.y, b3);
        }

        float accf[4][4];
#pragma unroll
        for (int j = 0; j < 4; j++) {
            float2 p = unpk(acc2[0][j]);
            float2 q = unpk(acc2[1][j]);
            accf[0][j] = p.x; accf[1][j] = p.y;
            accf[2][j] = q.x; accf[3][j] = q.y;
        }

#pragma unroll
        for (int i = 0; i < 4; i++) {
            int m = m0 + ty * 4 + i;
            int n = n0 + tx * 4;
            float* cp = &C[(size_t)m * N + n];
            if (n + 3 < N) {
                float4 v;
                v.x = accf[i][0] + bias[n + 0];
                v.y = accf[i][1] + bias[n + 1];
                v.z = accf[i][2] + bias[n + 2];
                v.w = accf[i][3] + bias[n + 3];
                *reinterpret_cast<float4*>(cp) = v;
            } else {
#pragma unroll
                for (int j = 0; j < 4; j++)
                    if (n + j < N) cp[j] = accf[i][j] + bias[n + j];
            }
        }
    }
}

// ---------------- layer-1 scan: 256 threads, 2 columns/thread (R7) ----------
#define U1REGJ 80
#define U1SMJ  20
#define H1P    104
#define ZSP    20
__global__ __launch_bounds__(256, 1)
void lstm_scan1(const float* __restrict__ zx, const float* __restrict__ U,
                float* __restrict__ hout)
{
    extern __shared__ __align__(16) float sm1[];
    float* U1sT = sm1;                       // [512 slots][U1SMJ]
    float* hT   = sm1 + 512 * U1SMJ;         // [2][4][H1P]
    float* zs   = hT + 2 * 4 * H1P;          // [128][ZSP]

    const int tid = threadIdx.x;
    const int j4 = tid >> 2;                 // 0..63
    const int k  = tid & 3;
    const int jA = (j4 < 50) ? j4 : 49;
    const int jB = jA + 50;
    const int colA = k * H1D + jA;
    const int colB = k * H1D + jB;
    const int b0 = blockIdx.x * 4;

    u64 UpA[U1REGJ / 2], UpB[U1REGJ / 2];
#pragma unroll
    for (int p = 0; p < U1REGJ / 2; ++p) {
        UpA[p] = pack2(U[(2 * p) * G1D + colA], U[(2 * p + 1) * G1D + colA]);
        UpB[p] = pack2(U[(2 * p) * G1D + colB], U[(2 * p + 1) * G1D + colB]);
    }
#pragma unroll
    for (int jj = 0; jj < U1SMJ; ++jj) {
        U1sT[tid * U1SMJ + jj]         = U[(U1REGJ + jj) * G1D + colA];
        U1sT[(256 + tid) * U1SMJ + jj] = U[(U1REGJ + jj) * G1D + colB];
    }
    for (int i = tid; i < 2 * 4 * H1P; i += 256) hT[i] = 0.f;

    float cA = 0.f, cB = 0.f;
    const float* zbA = zx + colA;
    const float* zbB = zx + colB;
    float zA0 = zbA[((size_t)0 * BATCH + b0 + 0) * G1D];
    float zA1 = zbA[((size_t)0 * BATCH + b0 + 1) * G1D];
    float zA2 = zbA[((size_t)0 * BATCH + b0 + 2) * G1D];
    float zA3 = zbA[((size_t)0 * BATCH + b0 + 3) * G1D];
    float zB0 = zbB[((size_t)0 * BATCH + b0 + 0) * G1D];
    float zB1 = zbB[((size_t)0 * BATCH + b0 + 1) * G1D];
    float zB2 = zbB[((size_t)0 * BATCH + b0 + 2) * G1D];
    float zB3 = zbB[((size_t)0 * BATCH + b0 + 3) * G1D];
    __syncthreads();

#pragma unroll 1
    for (int t = 0; t < T_SEQ; ++t) {
        int tn = (t + 1 < T_SEQ) ? (t + 1) : t;
        float nA0 = zbA[((size_t)tn * BATCH + b0 + 0) * G1D];
        float nA1 = zbA[((size_t)tn * BATCH + b0 + 1) * G1D];
        float nA2 = zbA[((size_t)tn * BATCH + b0 + 2) * G1D];
        float nA3 = zbA[((size_t)tn * BATCH + b0 + 3) * G1D];
        float nB0 = zbB[((size_t)tn * BATCH + b0 + 0) * G1D];
        float nB1 = zbB[((size_t)tn * BATCH + b0 + 1) * G1D];
        float nB2 = zbB[((size_t)tn * BATCH + b0 + 2) * G1D];
        float nB3 = zbB[((size_t)tn * BATCH + b0 + 3) * G1D];

        const float* hp = hT + (t & 1) * (4 * H1P);
        u64 aA0 = 0ull, aA1 = 0ull, aA2 = 0ull, aA3 = 0ull;
        u64 aB0 = 0ull, aB1 = 0ull, aB2 = 0ull, aB3 = 0ull;
#pragma unroll
        for (int p4 = 0; p4 < U1REGJ / 4; ++p4) {
            int j0 = 4 * p4;
            ulonglong2 h0 = *reinterpret_cast<const ulonglong2*>(&hp[0 * H1P + j0]);
            ulonglong2 h1 = *reinterpret_cast<const ulonglong2*>(&hp[1 * H1P + j0]);
            ulonglong2 h2 = *reinterpret_cast<const ulonglong2*>(&hp[2 * H1P + j0]);
            ulonglong2 h3 = *reinterpret_cast<const ulonglong2*>(&hp[3 * H1P + j0]);
            u64 ua = UpA[2 * p4], ub = UpA[2 * p4 + 1];
            u64 va = UpB[2 * p4], vb = UpB[2 * p4 + 1];
            ffma2(aA0, h0.x, ua); ffma2(aA0, h0.y, ub);
            ffma2(aA1, h1.x, ua); ffma2(aA1, h1.y, ub);
            ffma2(aA2, h2.x, ua); ffma2(aA2, h2.y, ub);
            ffma2(aA3, h3.x, ua); ffma2(aA3, h3.y, ub);
            ffma2(aB0, h0.x, va); ffma2(aB0, h0.y, vb);
            ffma2(aB1, h1.x, va); ffma2(aB1, h1.y, vb);
            ffma2(aB2, h2.x, va); ffma2(aB2, h2.y, vb);
            ffma2(aB3, h3.x, va); ffma2(aB3, h3.y, vb);
        }
#pragma unroll
        for (int q = 0; q < U1SMJ / 4; ++q) {
            int j0 = U1REGJ + 4 * q;
            ulonglong2 uA = *reinterpret_cast<const ulonglong2*>(&U1sT[tid * U1SMJ + 4 * q]);
            ulonglong2 uB = *reinterpret_cast<const ulonglong2*>(&U1sT[(256 + tid) * U1SMJ + 4 * q]);
            ulonglong2 h0 = *reinterpret_cast<const ulonglong2*>(&hp[0 * H1P + j0]);
            ulonglong2 h1 = *reinterpret_cast<const ulonglong2*>(&hp[1 * H1P + j0]);
            ulonglong2 h2 = *reinterpret_cast<const ulonglong2*>(&hp[2 * H1P + j0]);
            ulonglong2 h3 = *reinterpret_cast<const ulonglong2*>(&hp[3 * H1P + j0]);
            ffma2(aA0, h0.x, uA.x); ffma2(aA0, h0.y, uA.y);
            ffma2(aA1, h1.x, uA.x); ffma2(aA1, h1.y, uA.y);
            ffma2(aA2, h2.x, uA.x); ffma2(aA2, h2.y, uA.y);
            ffma2(aA3, h3.x, uA.x); ffma2(aA3, h3.y, uA.y);
            ffma2(aB0, h0.x, uB.x); ffma2(aB0, h0.y, uB.y);
            ffma2(aB1, h1.x, uB.x); ffma2(aB1, h1.y, uB.y);
            ffma2(aB2, h2.x, uB.x); ffma2(aB2, h2.y, uB.y);
            ffma2(aB3, h3.x, uB.x); ffma2(aB3, h3.y, uB.y);
        }
        float2 sA0 = unpk(aA0), sA1 = unpk(aA1), sA2 = unpk(aA2), sA3 = unpk(aA3);
        float2 sB0 = unpk(aB0), sB1 = unpk(aB1), sB2 = unpk(aB2), sB3 = unpk(aB3);
        float vA0 = sA0.x + sA0.y + zA0;
        float vA1 = sA1.x + sA1.y + zA1;
        float vA2 = sA2.x + sA2.y + zA2;
        float vA3 = sA3.x + sA3.y + zA3;
        float vB0 = sB0.x + sB0.y + zB0;
        float vB1 = sB1.x + sB1.y + zB1;
        float vB2 = sB2.x + sB2.y + zB2;
        float vB3 = sB3.x + sB3.y + zB3;
        if (k == 2) {
            vA0 = fmaxf(vA0, 0.f); vA1 = fmaxf(vA1, 0.f);
            vA2 = fmaxf(vA2, 0.f); vA3 = fmaxf(vA3, 0.f);
            vB0 = fmaxf(vB0, 0.f); vB1 = fmaxf(vB1, 0.f);
            vB2 = fmaxf(vB2, 0.f); vB3 = fmaxf(vB3, 0.f);
        } else {
            vA0 = fsig(vA0); vA1 = fsig(vA1); vA2 = fsig(vA2); vA3 = fsig(vA3);
            vB0 = fsig(vB0); vB1 = fsig(vB1); vB2 = fsig(vB2); vB3 = fsig(vB3);
        }
        *reinterpret_cast<float4*>(&zs[jA * ZSP + k * 4]) = make_float4(vA0, vA1, vA2, vA3);
        *reinterpret_cast<float4*>(&zs[jB * ZSP + k * 4]) = make_float4(vB0, vB1, vB2, vB3);
        __syncwarp();
        {
            float gi = zs[jA * ZSP + 0  + k];
            float gf = zs[jA * ZSP + 4  + k];
            float gg = zs[jA * ZSP + 8  + k];
            float go = zs[jA * ZSP + 12 + k];
            cA = fmaf(gf, cA, gi * gg);
            float h = go * fmaxf(cA, 0.f);
            hT[(1 - (t & 1)) * (4 * H1P) + k * H1P + jA] = h;
            if (j4 < 50) hout[((size_t)t * BATCH + b0 + k) * H1D + jA] = h;
        }
        {
            float gi = zs[jB * ZSP + 0  + k];
            float gf = zs[jB * ZSP + 4  + k];
            float gg = zs[jB * ZSP + 8  + k];
            float go = zs[jB * ZSP + 12 + k];
            cB = fmaf(gf, cB, gi * gg);
            float h = go * fmaxf(cB, 0.f);
            hT[(1 - (t & 1)) * (4 * H1P) + k * H1P + jB] = h;
            if (j4 < 50) hout[((size_t)t * BATCH + b0 + k) * H1D + jB] = h;
        }
        zA0 = nA0; zA1 = nA1; zA2 = nA2; zA3 = nA3;
        zB0 = nB0; zB1 = nB1; zB2 = nB2; zB3 = nB3;
        __syncthreads();
    }
}

// ---------------- layer-2 scan (R6-proven): 256 threads, 2 cols/thread ------
#define U2REGJ 80
#define U2SMJ  48
#define U2P    52
__global__ __launch_bounds__(256, 1)
void lstm_scan2(const float* __restrict__ zx, const float* __restrict__ U,
                float* __restrict__ h2out)
{
    extern __shared__ __align__(16) float sm2[];
    float* U2sT = sm2;                       // [512 slots][U2P]
    float* hT   = sm2 + 512 * U2P;           // [2][4][H2D]
    float* zs   = hT + 2 * 4 * H2D;          // [128][ZSP]

    const int tid = threadIdx.x;
    const int j  = tid >> 2;        // 0..63
    const int k  = tid & 3;
    const int jA = j, jB = j + 64;
    const int colA = k * H2D + jA;
    const int colB = k * H2D + jB;
    const int b0 = blockIdx.x * 4;

    u64 UpA[U2REGJ / 2], UpB[U2REGJ / 2];
#pragma unroll
    for (int p = 0; p < U2REGJ / 2; ++p) {
        UpA[p] = pack2(U[(2 * p) * G2D + colA], U[(2 * p + 1) * G2D + colA]);
        UpB[p] = pack2(U[(2 * p) * G2D + colB], U[(2 * p + 1) * G2D + colB]);
    }
    for (int idx = tid; idx < U2SMJ * G2D; idx += 256) {
        int r = idx >> 9;
        int cc = idx & 511;
        int jj = cc & 127, kk = cc >> 7;
        int slot = (jj < 64) ? (4 * jj + kk) : (256 + 4 * (jj - 64) + kk);
        U2sT[slot * U2P + r] = U[(size_t)(U2REGJ + r) * G2D + cc];
    }
    for (int i = tid; i < 2 * 4 * H2D; i += 256) hT[i] = 0.f;

    float cA = 0.f, cB = 0.f;
    const float* zbA = zx + colA;
    const float* zbB = zx + colB;
    float zA0 = zbA[((size_t)0 * BATCH + b0 + 0) * G2D];
    float zA1 = zbA[((size_t)0 * BATCH + b0 + 1) * G2D];
    float zA2 = zbA[((size_t)0 * BATCH + b0 + 2) * G2D];
    float zA3 = zbA[((size_t)0 * BATCH + b0 + 3) * G2D];
    float zB0 = zbB[((size_t)0 * BATCH + b0 + 0) * G2D];
    float zB1 = zbB[((size_t)0 * BATCH + b0 + 1) * G2D];
    float zB2 = zbB[((size_t)0 * BATCH + b0 + 2) * G2D];
    float zB3 = zbB[((size_t)0 * BATCH + b0 + 3) * G2D];
    __syncthreads();

#pragma unroll 1
    for (int t = 0; t < T_SEQ; ++t) {
        int tn = (t + 1 < T_SEQ) ? (t + 1) : t;
        float nA0 = zbA[((size_t)tn * BATCH + b0 + 0) * G2D];
        float nA1 = zbA[((size_t)tn * BATCH + b0 + 1) * G2D];
        float nA2 = zbA[((size_t)tn * BATCH + b0 + 2) * G2D];
        float nA3 = zbA[((size_t)tn * BATCH + b0 + 3) * G2D];
        float nB0 = zbB[((size_t)tn * BATCH + b0 + 0) * G2D];
        float nB1 = zbB[((size_t)tn * BATCH + b0 + 1) * G2D];
        float nB2 = zbB[((size_t)tn * BATCH + b0 + 2) * G2D];
        float nB3 = zbB[((size_t)tn * BATCH + b0 + 3) * G2D];

        const float* hp = hT + (t & 1) * (4 * H2D);
        u64 aA0 = 0ull, aA1 = 0ull, aA2 = 0ull, aA3 = 0ull;
        u64 aB0 = 0ull, aB1 = 0ull, aB2 = 0ull, aB3 = 0ull;
#pragma unroll
        for (int p4 = 0; p4 < U2REGJ / 4; ++p4) {
            int j0 = 4 * p4;
            ulonglong2 h0 = *reinterpret_cast<const ulonglong2*>(&hp[0 * H2D + j0]);
            ulonglong2 h1 = *reinterpret_cast<const ulonglong2*>(&hp[1 * H2D + j0]);
            ulonglong2 h2 = *reinterpret_cast<const ulonglong2*>(&hp[2 * H2D + j0]);
            ulonglong2 h3 = *reinterpret_cast<const ulonglong2*>(&hp[3 * H2D + j0]);
            u64 ua = UpA[2 * p4], ub = UpA[2 * p4 + 1];
            u64 va = UpB[2 * p4], vb = UpB[2 * p4 + 1];
            ffma2(aA0, h0.x, ua); ffma2(aA0, h0.y, ub);
            ffma2(aA1, h1.x, ua); ffma2(aA1, h1.y, ub);
            ffma2(aA2, h2.x, ua); ffma2(aA2, h2.y, ub);
            ffma2(aA3, h3.x, ua); ffma2(aA3, h3.y, ub);
            ffma2(aB0, h0.x, va); ffma2(aB0, h0.y, vb);
            ffma2(aB1, h1.x, va); ffma2(aB1, h1.y, vb);
            ffma2(aB2, h2.x, va); ffma2(aB2, h2.y, vb);
            ffma2(aB3, h3.x, va); ffma2(aB3, h3.y, vb);
        }
#pragma unroll
        for (int q = 0; q < U2SMJ / 4; ++q) {
            int j0 = U2REGJ + 4 * q;
            ulonglong2 uA = *reinterpret_cast<const ulonglong2*>(&U2sT[tid * U2P + 4 * q]);
            ulonglong2 uB = *reinterpret_cast<const ulonglong2*>(&U2sT[(256 + tid) * U2P + 4 * q]);
            ulonglong2 h0 = *reinterpret_cast<const ulonglong2*>(&hp[0 * H2D + j0]);
            ulonglong2 h1 = *reinterpret_cast<const ulonglong2*>(&hp[1 * H2D + j0]);
            ulonglong2 h2 = *reinterpret_cast<const ulonglong2*>(&hp[2 * H2D + j0]);
            ulonglong2 h3 = *reinterpret_cast<const ulonglong2*>(&hp[3 * H2D + j0]);
            ffma2(aA0, h0.x, uA.x); ffma2(aA0, h0.y, uA.y);
            ffma2(aA1, h1.x, uA.x); ffma2(aA1, h1.y, uA.y);
            ffma2(aA2, h2.x, uA.x); ffma2(aA2, h2.y, uA.y);
            ffma2(aA3, h3.x, uA.x); ffma2(aA3, h3.y, uA.y);
            ffma2(aB0, h0.x, uB.x); ffma2(aB0, h0.y, uB.y);
            ffma2(aB1, h1.x, uB.x); ffma2(aB1, h1.y, uB.y);
            ffma2(aB2, h2.x, uB.x); ffma2(aB2, h2.y, uB.y);
            ffma2(aB3, h3.x, uB.x); ffma2(aB3, h3.y, uB.y);
        }
        float2 sA0 = unpk(aA0), sA1 = unpk(aA1), sA2 = unpk(aA2), sA3 = unpk(aA3);
        float2 sB0 = unpk(aB0), sB1 = unpk(aB1), sB2 = unpk(aB2), sB3 = unpk(aB3);
        float vA0 = sA0.x + sA0.y + zA0;
        float vA1 = sA1.x + sA1.y + zA1;
        float vA2 = sA2.x + sA2.y + zA2;
        float vA3 = sA3.x + sA3.y + zA3;
        float vB0 = sB0.x + sB0.y + zB0;
        float vB1 = sB1.x + sB1.y + zB1;
        float vB2 = sB2.x + sB2.y + zB2;
        float vB3 = sB3.x + sB3.y + zB3;
        if (k == 2) {
            vA0 = fmaxf(vA0, 0.f); vA1 = fmaxf(vA1, 0.f);
            vA2 = fmaxf(vA2, 0.f); vA3 = fmaxf(vA3, 0.f);
            vB0 = fmaxf(vB0, 0.f); vB1 = fmaxf(vB1, 0.f);
            vB2 = fmaxf(vB2, 0.f); vB3 = fmaxf(vB3, 0.f);
        } else {
            vA0 = fsig(vA0); vA1 = fsig(vA1); vA2 = fsig(vA2); vA3 = fsig(vA3);
            vB0 = fsig(vB0); vB1 = fsig(vB1); vB2 = fsig(vB2); vB3 = fsig(vB3);
        }
        *reinterpret_cast<float4*>(&zs[jA * ZSP + k * 4]) = make_float4(vA0, vA1, vA2, vA3);
        *reinterpret_cast<float4*>(&zs[jB * ZSP + k * 4]) = make_float4(vB0, vB1, vB2, vB3);
        __syncwarp();
        {
            float gi = zs[jA * ZSP + 0  + k];
            float gf = zs[jA * ZSP + 4  + k];
            float gg = zs[jA * ZSP + 8  + k];
            float go = zs[jA * ZSP + 12 + k];
            cA = fmaf(gf, cA, gi * gg);
            float h = go * fmaxf(cA, 0.f);
            hT[(1 - (t & 1)) * (4 * H2D) + k * H2D + jA] = h;
            if (t == T_SEQ - 1) h2out[(b0 + k) * H2D + jA] = h;
        }
        {
            float gi = zs[jB * ZSP + 0  + k];
            float gf = zs[jB * ZSP + 4  + k];
            float gg = zs[jB * ZSP + 8  + k];
            float go = zs[jB * ZSP + 12 + k];
            cB = fmaf(gf, cB, gi * gg);
            float h = go * fmaxf(cB, 0.f);
            hT[(1 - (t & 1)) * (4 * H2D) + k * H2D + jB] = h;
            if (t == T_SEQ - 1) h2out[(b0 + k) * H2D + jB] = h;
        }
        zA0 = nA0; zA1 = nA1; zA2 = nA2; zA3 = nA3;
        zB0 = nB0; zB1 = nB1; zB2 = nB2; zB3 = nB3;
        __syncthreads();
    }
}

// ---------------- dense head + softmax -------------------------------------
__global__ void head_kernel(const float* __restrict__ h2, const float* __restrict__ Wd,
                            const float* __restrict__ bd, float* __restrict__ out)
{
    __shared__ float hsh[H2D];
    const int b = blockIdx.x;
    const int lane = threadIdx.x;
    for (int j = lane; j < H2D; j += 32) hsh[j] = h2[b * H2D + j];
    __syncthreads();

    float acc = 0.f;
    if (lane < NC) {
        acc = bd[lane];
#pragma unroll
        for (int j = 0; j < H2D; ++j) acc = fmaf(hsh[j], Wd[j * NC + lane], acc);
    }
    float v = (lane < NC) ? acc : -FLT_MAX;
#pragma unroll
    for (int off = 16; off > 0; off >>= 1)
        v = fmaxf(v, __shfl_xor_sync(0xffffffffu, v, off));
    float e = (lane < NC) ? expf(acc - v) : 0.f;
    float s = e;
#pragma unroll
    for (int off = 16; off > 0; off >>= 1)
        s += __shfl_xor_sync(0xffffffffu, s, off);
    if (lane < NC) out[b * NC + lane] = e / s;
}

// ---------------- launch ----------------------------------------------------
extern "C" void kernel_launch(void* const* d_in, const int* in_sizes, int n_in,
                              void* d_out, int out_size)
{
    const float* x  = (const float*)d_in[0];
    const float* W1 = (const float*)d_in[1];
    const float* U1 = (const float*)d_in[2];
    const float* b1 = (const float*)d_in[3];
    const float* W2 = (const float*)d_in[4];
    const float* U2 = (const float*)d_in[5];
    const float* b2 = (const float*)d_in[6];
    const float* Wd = (const float*)d_in[7];
    const float* bd = (const float*)d_in[8];
    float* out = (float*)d_out;

    const int gemm_smem  = (KMAX * AP + KMAX * BN) * 4;                    // 67584
    const int scan1_smem = (512 * U1SMJ + 2 * 4 * H1P + 128 * ZSP) * 4;    // 54528
    const int scan2_smem = (512 * U2P + 2 * 4 * H2D + 128 * ZSP) * 4;      // 120832
    cudaFuncSetAttribute(gemm_ff,    cudaFuncAttributeMaxDynamicSharedMemorySize, gemm_smem);
    cudaFuncSetAttribute(lstm_scan1, cudaFuncAttributeMaxDynamicSharedMemorySize, scan1_smem);
    cudaFuncSetAttribute(lstm_scan2, cudaFuncAttributeMaxDynamicSharedMemorySize, scan2_smem);

    float *zx1p, *h1p, *zx2p, *h2p;
    cudaGetSymbolAddress((void**)&zx1p, g_zx1);
    cudaGetSymbolAddress((void**)&h1p,  g_h1);
    cudaGetSymbolAddress((void**)&zx2p, g_zx2);
    cudaGetSymbolAddress((void**)&h2p,  g_h2);

    const int M = T_SEQ * BATCH;

    gemm_ff<<<M / BM, 256, gemm_smem>>>(x, W1, b1, zx1p, M, G1D, IND, 1);

    lstm_scan1<<<BATCH / 4, 256, scan1_smem>>>(zx1p, U1, h1p);

    gemm_ff<<<M / BM, 256, gemm_smem>>>(h1p, W2, b2, zx2p, M, G2D, H1D, 0);

    lstm_scan2<<<BATCH / 4, 256, scan2_smem>>>(zx2p, U2, h2p);

    head_kernel<<<BATCH, 32>>>(h2p, Wd, bd, out);
}

// round 11
// speedup vs baseline: 1.0250x; 1.0250x over previous
#include <cuda_runtime.h>
#include <math.h>
#include <float.h>

// Problem dims
#define T_SEQ 256
#define BATCH 512
#define IND   128
#define H1D   100
#define G1D   400     // 4*H1
#define H2D   128
#define G2D   512     // 4*H2
#define NC    19

typedef unsigned long long u64;

__device__ __forceinline__ void ffma2(u64 &d, u64 a, u64 b) {
    asm("fma.rn.f32x2 %0, %1, %2, %0;" : "+l"(d) : "l"(a), "l"(b));
}
__device__ __forceinline__ u64 pack2(float x, float y) {
    u64 r; asm("mov.b64 %0, {%1, %2};" : "=l"(r) : "f"(x), "f"(y)); return r;
}
__device__ __forceinline__ float2 unpk(u64 v) {
    float2 r; asm("mov.b64 {%0, %1}, %2;" : "=f"(r.x), "=f"(r.y) : "l"(v)); return r;
}
__device__ __forceinline__ float fsig(float a) {
    return __fdividef(1.f, 1.f + __expf(-a));
}

// ---------------- scratch ---------------------------------------------------
__device__ float g_zx1[256u*512u*400u];   // [(t,b)][G1]
__device__ float g_h1 [256u*512u*100u];   // [(t,b)][H1]
__device__ float g_zx2[256u*512u*512u];   // [(t,b)][G2]
__device__ float g_h2 [512u*128u];        // [B][H2]

// ---------------- feedforward GEMM: A-resident n-loop, k-pair packed --------
// f32x2 lanes = (even-k, odd-k) partial sums. As2/Bs2 hold k-pairs as u64
// (same smem bytes as scalar). Inner loop: 4 LDS.128 + 16 FFMA2 per k-pair
// (20 issues / 32 FMA, no packs). Lane-add at epilogue.
#define BM 64
#define BN 64
#define KPMAX 64     // max k-pairs (K<=128)
#define APM 66       // As2 row stride in u64 (even -> 16B-aligned rows)

__global__ __launch_bounds__(256, 3)
void gemm_ff(const float* __restrict__ A, const float* __restrict__ Bw,
             const float* __restrict__ bias, float* __restrict__ C,
             int M, int N, int K, int mode)
{
    extern __shared__ __align__(16) char smraw[];
    u64* As2 = reinterpret_cast<u64*>(smraw);      // [KPMAX][APM]
    u64* Bs2 = As2 + KPMAX * APM;                  // [KPMAX][BN]

    const int tid = threadIdx.x;
    const int m0 = blockIdx.x * BM;
    const int tx = tid & 15, ty = tid >> 4;
    const int kp = K >> 1;        // k-pairs (K=128 or 100, both even)
    const int nf4 = K >> 2;       // float4 groups per A row

    // load A tile once: float4 LDG -> two u64 k-pair entries
    for (int idx = tid; idx < BM * nf4; idx += 256) {
        int mloc = idx / nf4;
        int f = idx - mloc * nf4;
        int m = m0 + mloc;
        size_t arow;
        if (mode) { int t = m >> 9; int b = m & 511; arow = ((size_t)(b * T_SEQ + t)) * IND; }
        else      { arow = (size_t)m * K; }
        float4 v = *reinterpret_cast<const float4*>(&A[arow + 4 * f]);
        As2[(2 * f + 0) * APM + mloc] = pack2(v.x, v.y);
        As2[(2 * f + 1) * APM + mloc] = pack2(v.z, v.w);
    }

    const int ntiles = (N + BN - 1) / BN;
    for (int nt = 0; nt < ntiles; ++nt) {
        const int n0 = nt * BN;
        if (nt > 0) __syncthreads();     // prior compute done before Bs2 overwrite
        for (int idx = tid; idx < kp * BN; idx += 256) {
            int kk = idx >> 6;
            int n = idx & 63;
            int gn = n0 + n;
            float b0 = 0.f, b1 = 0.f;
            if (gn < N) {
                b0 = Bw[(size_t)(2 * kk + 0) * N + gn];
                b1 = Bw[(size_t)(2 * kk + 1) * N + gn];
            }
            Bs2[kk * BN + n] = pack2(b0, b1);
        }
        __syncthreads();                 // tiles ready

        u64 acc2[4][4];
#pragma unroll
        for (int i = 0; i < 4; i++)
#pragma unroll
            for (int j = 0; j < 4; j++) acc2[i][j] = 0ull;

#pragma unroll 4
        for (int kk = 0; kk < kp; ++kk) {
            ulonglong2 a01 = *reinterpret_cast<const ulonglong2*>(&As2[kk * APM + ty * 4]);
            ulonglong2 a23 = *reinterpret_cast<const ulonglong2*>(&As2[kk * APM + ty * 4 + 2]);
            ulonglong2 b01 = *reinterpret_cast<const ulonglong2*>(&Bs2[kk * BN + tx * 4]);
            ulonglong2 b23 = *reinterpret_cast<const ulonglong2*>(&Bs2[kk * BN + tx * 4 + 2]);
            ffma2(acc2[0][0], a01.x, b01.x); ffma2(acc2[0][1], a01.x, b01.y);
            ffma2(acc2[0][2], a01.x, b23.x); ffma2(acc2[0][3], a01.x, b23.y);
            ffma2(acc2[1][0], a01.y, b01.x); ffma2(acc2[1][1], a01.y, b01.y);
            ffma2(acc2[1][2], a01.y, b23.x); ffma2(acc2[1][3], a01.y, b23.y);
            ffma2(acc2[2][0], a23.x, b01.x); ffma2(acc2[2][1], a23.x, b01.y);
            ffma2(acc2[2][2], a23.x, b23.x); ffma2(acc2[2][3], a23.x, b23.y);
            ffma2(acc2[3][0], a23.y, b01.x); ffma2(acc2[3][1], a23.y, b01.y);
            ffma2(acc2[3][2], a23.y, b23.x); ffma2(acc2[3][3], a23.y, b23.y);
        }

        const int n = n0 + tx * 4;
#pragma unroll
        for (int i = 0; i < 4; i++) {
            int m = m0 + ty * 4 + i;
            float2 c0 = unpk(acc2[i][0]);
            float2 c1 = unpk(acc2[i][1]);
            float2 c2 = unpk(acc2[i][2]);
            float2 c3 = unpk(acc2[i][3]);
            float* cp = &C[(size_t)m * N + n];
            if (n + 3 < N) {
                float4 v;
                v.x = c0.x + c0.y + bias[n + 0];
                v.y = c1.x + c1.y + bias[n + 1];
                v.z = c2.x + c2.y + bias[n + 2];
                v.w = c3.x + c3.y + bias[n + 3];
                *reinterpret_cast<float4*>(cp) = v;
            } else {
                float vv[4] = {c0.x + c0.y, c1.x + c1.y, c2.x + c2.y, c3.x + c3.y};
#pragma unroll
                for (int jj = 0; jj < 4; jj++)
                    if (n + jj < N) cp[jj] = vv[jj] + bias[n + jj];
            }
        }
    }
}

// ---------------- layer-1 scan: 256 threads, 2 columns/thread (R7) ----------
#define U1REGJ 80
#define U1SMJ  20
#define H1P    104
#define ZSP    20
__global__ __launch_bounds__(256, 1)
void lstm_scan1(const float* __restrict__ zx, const float* __restrict__ U,
                float* __restrict__ hout)
{
    extern __shared__ __align__(16) float sm1[];
    float* U1sT = sm1;                       // [512 slots][U1SMJ]
    float* hT   = sm1 + 512 * U1SMJ;         // [2][4][H1P]
    float* zs   = hT + 2 * 4 * H1P;          // [128][ZSP]

    const int tid = threadIdx.x;
    const int j4 = tid >> 2;                 // 0..63
    const int k  = tid & 3;
    const int jA = (j4 < 50) ? j4 : 49;
    const int jB = jA + 50;
    const int colA = k * H1D + jA;
    const int colB = k * H1D + jB;
    const int b0 = blockIdx.x * 4;

    u64 UpA[U1REGJ / 2], UpB[U1REGJ / 2];
#pragma unroll
    for (int p = 0; p < U1REGJ / 2; ++p) {
        UpA[p] = pack2(U[(2 * p) * G1D + colA], U[(2 * p + 1) * G1D + colA]);
        UpB[p] = pack2(U[(2 * p) * G1D + colB], U[(2 * p + 1) * G1D + colB]);
    }
#pragma unroll
    for (int jj = 0; jj < U1SMJ; ++jj) {
        U1sT[tid * U1SMJ + jj]         = U[(U1REGJ + jj) * G1D + colA];
        U1sT[(256 + tid) * U1SMJ + jj] = U[(U1REGJ + jj) * G1D + colB];
    }
    for (int i = tid; i < 2 * 4 * H1P; i += 256) hT[i] = 0.f;

    float cA = 0.f, cB = 0.f;
    const float* zbA = zx + colA;
    const float* zbB = zx + colB;
    float zA0 = zbA[((size_t)0 * BATCH + b0 + 0) * G1D];
    float zA1 = zbA[((size_t)0 * BATCH + b0 + 1) * G1D];
    float zA2 = zbA[((size_t)0 * BATCH + b0 + 2) * G1D];
    float zA3 = zbA[((size_t)0 * BATCH + b0 + 3) * G1D];
    float zB0 = zbB[((size_t)0 * BATCH + b0 + 0) * G1D];
    float zB1 = zbB[((size_t)0 * BATCH + b0 + 1) * G1D];
    float zB2 = zbB[((size_t)0 * BATCH + b0 + 2) * G1D];
    float zB3 = zbB[((size_t)0 * BATCH + b0 + 3) * G1D];
    __syncthreads();

#pragma unroll 1
    for (int t = 0; t < T_SEQ; ++t) {
        int tn = (t + 1 < T_SEQ) ? (t + 1) : t;
        float nA0 = zbA[((size_t)tn * BATCH + b0 + 0) * G1D];
        float nA1 = zbA[((size_t)tn * BATCH + b0 + 1) * G1D];
        float nA2 = zbA[((size_t)tn * BATCH + b0 + 2) * G1D];
        float nA3 = zbA[((size_t)tn * BATCH + b0 + 3) * G1D];
        float nB0 = zbB[((size_t)tn * BATCH + b0 + 0) * G1D];
        float nB1 = zbB[((size_t)tn * BATCH + b0 + 1) * G1D];
        float nB2 = zbB[((size_t)tn * BATCH + b0 + 2) * G1D];
        float nB3 = zbB[((size_t)tn * BATCH + b0 + 3) * G1D];

        const float* hp = hT + (t & 1) * (4 * H1P);
        u64 aA0 = 0ull, aA1 = 0ull, aA2 = 0ull, aA3 = 0ull;
        u64 aB0 = 0ull, aB1 = 0ull, aB2 = 0ull, aB3 = 0ull;
#pragma unroll
        for (int p4 = 0; p4 < U1REGJ / 4; ++p4) {
            int j0 = 4 * p4;
            ulonglong2 h0 = *reinterpret_cast<const ulonglong2*>(&hp[0 * H1P + j0]);
            ulonglong2 h1 = *reinterpret_cast<const ulonglong2*>(&hp[1 * H1P + j0]);
            ulonglong2 h2 = *reinterpret_cast<const ulonglong2*>(&hp[2 * H1P + j0]);
            ulonglong2 h3 = *reinterpret_cast<const ulonglong2*>(&hp[3 * H1P + j0]);
            u64 ua = UpA[2 * p4], ub = UpA[2 * p4 + 1];
            u64 va = UpB[2 * p4], vb = UpB[2 * p4 + 1];
            ffma2(aA0, h0.x, ua); ffma2(aA0, h0.y, ub);
            ffma2(aA1, h1.x, ua); ffma2(aA1, h1.y, ub);
            ffma2(aA2, h2.x, ua); ffma2(aA2, h2.y, ub);
            ffma2(aA3, h3.x, ua); ffma2(aA3, h3.y, ub);
            ffma2(aB0, h0.x, va); ffma2(aB0, h0.y, vb);
            ffma2(aB1, h1.x, va); ffma2(aB1, h1.y, vb);
            ffma2(aB2, h2.x, va); ffma2(aB2, h2.y, vb);
            ffma2(aB3, h3.x, va); ffma2(aB3, h3.y, vb);
        }
#pragma unroll
        for (int q = 0; q < U1SMJ / 4; ++q) {
            int j0 = U1REGJ + 4 * q;
            ulonglong2 uA = *reinterpret_cast<const ulonglong2*>(&U1sT[tid * U1SMJ + 4 * q]);
            ulonglong2 uB = *reinterpret_cast<const ulonglong2*>(&U1sT[(256 + tid) * U1SMJ + 4 * q]);
            ulonglong2 h0 = *reinterpret_cast<const ulonglong2*>(&hp[0 * H1P + j0]);
            ulonglong2 h1 = *reinterpret_cast<const ulonglong2*>(&hp[1 * H1P + j0]);
            ulonglong2 h2 = *reinterpret_cast<const ulonglong2*>(&hp[2 * H1P + j0]);
            ulonglong2 h3 = *reinterpret_cast<const ulonglong2*>(&hp[3 * H1P + j0]);
            ffma2(aA0, h0.x, uA.x); ffma2(aA0, h0.y, uA.y);
            ffma2(aA1, h1.x, uA.x); ffma2(aA1, h1.y, uA.y);
            ffma2(aA2, h2.x, uA.x); ffma2(aA2, h2.y, uA.y);
            ffma2(aA3, h3.x, uA.x); ffma2(aA3, h3.y, uA.y);
            ffma2(aB0, h0.x, uB.x); ffma2(aB0, h0.y, uB.y);
            ffma2(aB1, h1.x, uB.x); ffma2(aB1, h1.y, uB.y);
            ffma2(aB2, h2.x, uB.x); ffma2(aB2, h2.y, uB.y);
            ffma2(aB3, h3.x, uB.x); ffma2(aB3, h3.y, uB.y);
        }
        float2 sA0 = unpk(aA0), sA1 = unpk(aA1), sA2 = unpk(aA2), sA3 = unpk(aA3);
        float2 sB0 = unpk(aB0), sB1 = unpk(aB1), sB2 = unpk(aB2), sB3 = unpk(aB3);
        float vA0 = sA0.x + sA0.y + zA0;
        float vA1 = sA1.x + sA1.y + zA1;
        float vA2 = sA2.x + sA2.y + zA2;
        float vA3 = sA3.x + sA3.y + zA3;
        float vB0 = sB0.x + sB0.y + zB0;
        float vB1 = sB1.x + sB1.y + zB1;
        float vB2 = sB2.x + sB2.y + zB2;
        float vB3 = sB3.x + sB3.y + zB3;
        if (k == 2) {
            vA0 = fmaxf(vA0, 0.f); vA1 = fmaxf(vA1, 0.f);
            vA2 = fmaxf(vA2, 0.f); vA3 = fmaxf(vA3, 0.f);
            vB0 = fmaxf(vB0, 0.f); vB1 = fmaxf(vB1, 0.f);
            vB2 = fmaxf(vB2, 0.f); vB3 = fmaxf(vB3, 0.f);
        } else {
            vA0 = fsig(vA0); vA1 = fsig(vA1); vA2 = fsig(vA2); vA3 = fsig(vA3);
            vB0 = fsig(vB0); vB1 = fsig(vB1); vB2 = fsig(vB2); vB3 = fsig(vB3);
        }
        *reinterpret_cast<float4*>(&zs[jA * ZSP + k * 4]) = make_float4(vA0, vA1, vA2, vA3);
        *reinterpret_cast<float4*>(&zs[jB * ZSP + k * 4]) = make_float4(vB0, vB1, vB2, vB3);
        __syncwarp();
        {
            float gi = zs[jA * ZSP + 0  + k];
            float gf = zs[jA * ZSP + 4  + k];
            float gg = zs[jA * ZSP + 8  + k];
            float go = zs[jA * ZSP + 12 + k];
            cA = fmaf(gf, cA, gi * gg);
            float h = go * fmaxf(cA, 0.f);
            hT[(1 - (t & 1)) * (4 * H1P) + k * H1P + jA] = h;
            if (j4 < 50) hout[((size_t)t * BATCH + b0 + k) * H1D + jA] = h;
        }
        {
            float gi = zs[jB * ZSP + 0  + k];
            float gf = zs[jB * ZSP + 4  + k];
            float gg = zs[jB * ZSP + 8  + k];
            float go = zs[jB * ZSP + 12 + k];
            cB = fmaf(gf, cB, gi * gg);
            float h = go * fmaxf(cB, 0.f);
            hT[(1 - (t & 1)) * (4 * H1P) + k * H1P + jB] = h;
            if (j4 < 50) hout[((size_t)t * BATCH + b0 + k) * H1D + jB] = h;
        }
        zA0 = nA0; zA1 = nA1; zA2 = nA2; zA3 = nA3;
        zB0 = nB0; zB1 = nB1; zB2 = nB2; zB3 = nB3;
        __syncthreads();
    }
}

// ---------------- layer-2 scan (R6-proven): 256 threads, 2 cols/thread ------
#define U2REGJ 80
#define U2SMJ  48
#define U2P    52
__global__ __launch_bounds__(256, 1)
void lstm_scan2(const float* __restrict__ zx, const float* __restrict__ U,
                float* __restrict__ h2out)
{
    extern __shared__ __align__(16) float sm2[];
    float* U2sT = sm2;                       // [512 slots][U2P]
    float* hT   = sm2 + 512 * U2P;           // [2][4][H2D]
    float* zs   = hT + 2 * 4 * H2D;          // [128][ZSP]

    const int tid = threadIdx.x;
    const int j  = tid >> 2;        // 0..63
    const int k  = tid & 3;
    const int jA = j, jB = j + 64;
    const int colA = k * H2D + jA;
    const int colB = k * H2D + jB;
    const int b0 = blockIdx.x * 4;

    u64 UpA[U2REGJ / 2], UpB[U2REGJ / 2];
#pragma unroll
    for (int p = 0; p < U2REGJ / 2; ++p) {
        UpA[p] = pack2(U[(2 * p) * G2D + colA], U[(2 * p + 1) * G2D + colA]);
        UpB[p] = pack2(U[(2 * p) * G2D + colB], U[(2 * p + 1) * G2D + colB]);
    }
    for (int idx = tid; idx < U2SMJ * G2D; idx += 256) {
        int r = idx >> 9;
        int cc = idx & 511;
        int jj = cc & 127, kk = cc >> 7;
        int slot = (jj < 64) ? (4 * jj + kk) : (256 + 4 * (jj - 64) + kk);
        U2sT[slot * U2P + r] = U[(size_t)(U2REGJ + r) * G2D + cc];
    }
    for (int i = tid; i < 2 * 4 * H2D; i += 256) hT[i] = 0.f;

    float cA = 0.f, cB = 0.f;
    const float* zbA = zx + colA;
    const float* zbB = zx + colB;
    float zA0 = zbA[((size_t)0 * BATCH + b0 + 0) * G2D];
    float zA1 = zbA[((size_t)0 * BATCH + b0 + 1) * G2D];
    float zA2 = zbA[((size_t)0 * BATCH + b0 + 2) * G2D];
    float zA3 = zbA[((size_t)0 * BATCH + b0 + 3) * G2D];
    float zB0 = zbB[((size_t)0 * BATCH + b0 + 0) * G2D];
    float zB1 = zbB[((size_t)0 * BATCH + b0 + 1) * G2D];
    float zB2 = zbB[((size_t)0 * BATCH + b0 + 2) * G2D];
    float zB3 = zbB[((size_t)0 * BATCH + b0 + 3) * G2D];
    __syncthreads();

#pragma unroll 1
    for (int t = 0; t < T_SEQ; ++t) {
        int tn = (t + 1 < T_SEQ) ? (t + 1) : t;
        float nA0 = zbA[((size_t)tn * BATCH + b0 + 0) * G2D];
        float nA1 = zbA[((size_t)tn * BATCH + b0 + 1) * G2D];
        float nA2 = zbA[((size_t)tn * BATCH + b0 + 2) * G2D];
        float nA3 = zbA[((size_t)tn * BATCH + b0 + 3) * G2D];
        float nB0 = zbB[((size_t)tn * BATCH + b0 + 0) * G2D];
        float nB1 = zbB[((size_t)tn * BATCH + b0 + 1) * G2D];
        float nB2 = zbB[((size_t)tn * BATCH + b0 + 2) * G2D];
        float nB3 = zbB[((size_t)tn * BATCH + b0 + 3) * G2D];

        const float* hp = hT + (t & 1) * (4 * H2D);
        u64 aA0 = 0ull, aA1 = 0ull, aA2 = 0ull, aA3 = 0ull;
        u64 aB0 = 0ull, aB1 = 0ull, aB2 = 0ull, aB3 = 0ull;
#pragma unroll
        for (int p4 = 0; p4 < U2REGJ / 4; ++p4) {
            int j0 = 4 * p4;
            ulonglong2 h0 = *reinterpret_cast<const ulonglong2*>(&hp[0 * H2D + j0]);
            ulonglong2 h1 = *reinterpret_cast<const ulonglong2*>(&hp[1 * H2D + j0]);
            ulonglong2 h2 = *reinterpret_cast<const ulonglong2*>(&hp[2 * H2D + j0]);
            ulonglong2 h3 = *reinterpret_cast<const ulonglong2*>(&hp[3 * H2D + j0]);
            u64 ua = UpA[2 * p4], ub = UpA[2 * p4 + 1];
            u64 va = UpB[2 * p4], vb = UpB[2 * p4 + 1];
            ffma2(aA0, h0.x, ua); ffma2(aA0, h0.y, ub);
            ffma2(aA1, h1.x, ua); ffma2(aA1, h1.y, ub);
            ffma2(aA2, h2.x, ua); ffma2(aA2, h2.y, ub);
            ffma2(aA3, h3.x, ua); ffma2(aA3, h3.y, ub);
            ffma2(aB0, h0.x, va); ffma2(aB0, h0.y, vb);
            ffma2(aB1, h1.x, va); ffma2(aB1, h1.y, vb);
            ffma2(aB2, h2.x, va); ffma2(aB2, h2.y, vb);
            ffma2(aB3, h3.x, va); ffma2(aB3, h3.y, vb);
        }
#pragma unroll
        for (int q = 0; q < U2SMJ / 4; ++q) {
            int j0 = U2REGJ + 4 * q;
            ulonglong2 uA = *reinterpret_cast<const ulonglong2*>(&U2sT[tid * U2P + 4 * q]);
            ulonglong2 uB = *reinterpret_cast<const ulonglong2*>(&U2sT[(256 + tid) * U2P + 4 * q]);
            ulonglong2 h0 = *reinterpret_cast<const ulonglong2*>(&hp[0 * H2D + j0]);
            ulonglong2 h1 = *reinterpret_cast<const ulonglong2*>(&hp[1 * H2D + j0]);
            ulonglong2 h2 = *reinterpret_cast<const ulonglong2*>(&hp[2 * H2D + j0]);
            ulonglong2 h3 = *reinterpret_cast<const ulonglong2*>(&hp[3 * H2D + j0]);
            ffma2(aA0, h0.x, uA.x); ffma2(aA0, h0.y, uA.y);
            ffma2(aA1, h1.x, uA.x); ffma2(aA1, h1.y, uA.y);
            ffma2(aA2, h2.x, uA.x); ffma2(aA2, h2.y, uA.y);
            ffma2(aA3, h3.x, uA.x); ffma2(aA3, h3.y, uA.y);
            ffma2(aB0, h0.x, uB.x); ffma2(aB0, h0.y, uB.y);
            ffma2(aB1, h1.x, uB.x); ffma2(aB1, h1.y, uB.y);
            ffma2(aB2, h2.x, uB.x); ffma2(aB2, h2.y, uB.y);
            ffma2(aB3, h3.x, uB.x); ffma2(aB3, h3.y, uB.y);
        }
        float2 sA0 = unpk(aA0), sA1 = unpk(aA1), sA2 = unpk(aA2), sA3 = unpk(aA3);
        float2 sB0 = unpk(aB0), sB1 = unpk(aB1), sB2 = unpk(aB2), sB3 = unpk(aB3);
        float vA0 = sA0.x + sA0.y + zA0;
        float vA1 = sA1.x + sA1.y + zA1;
        float vA2 = sA2.x + sA2.y + zA2;
        float vA3 = sA3.x + sA3.y + zA3;
        float vB0 = sB0.x + sB0.y + zB0;
        float vB1 = sB1.x + sB1.y + zB1;
        float vB2 = sB2.x + sB2.y + zB2;
        float vB3 = sB3.x + sB3.y + zB3;
        if (k == 2) {
            vA0 = fmaxf(vA0, 0.f); vA1 = fmaxf(vA1, 0.f);
            vA2 = fmaxf(vA2, 0.f); vA3 = fmaxf(vA3, 0.f);
            vB0 = fmaxf(vB0, 0.f); vB1 = fmaxf(vB1, 0.f);
            vB2 = fmaxf(vB2, 0.f); vB3 = fmaxf(vB3, 0.f);
        } else {
            vA0 = fsig(vA0); vA1 = fsig(vA1); vA2 = fsig(vA2); vA3 = fsig(vA3);
            vB0 = fsig(vB0); vB1 = fsig(vB1); vB2 = fsig(vB2); vB3 = fsig(vB3);
        }
        *reinterpret_cast<float4*>(&zs[jA * ZSP + k * 4]) = make_float4(vA0, vA1, vA2, vA3);
        *reinterpret_cast<float4*>(&zs[jB * ZSP + k * 4]) = make_float4(vB0, vB1, vB2, vB3);
        __syncwarp();
        {
            float gi = zs[jA * ZSP + 0  + k];
            float gf = zs[jA * ZSP + 4  + k];
            float gg = zs[jA * ZSP + 8  + k];
            float go = zs[jA * ZSP + 12 + k];
            cA = fmaf(gf, cA, gi * gg);
            float h = go * fmaxf(cA, 0.f);
            hT[(1 - (t & 1)) * (4 * H2D) + k * H2D + jA] = h;
            if (t == T_SEQ - 1) h2out[(b0 + k) * H2D + jA] = h;
        }
        {
            float gi = zs[jB * ZSP + 0  + k];
            float gf = zs[jB * ZSP + 4  + k];
            float gg = zs[jB * ZSP + 8  + k];
            float go = zs[jB * ZSP + 12 + k];
            cB = fmaf(gf, cB, gi * gg);
            float h = go * fmaxf(cB, 0.f);
            hT[(1 - (t & 1)) * (4 * H2D) + k * H2D + jB] = h;
            if (t == T_SEQ - 1) h2out[(b0 + k) * H2D + jB] = h;
        }
        zA0 = nA0; zA1 = nA1; zA2 = nA2; zA3 = nA3;
        zB0 = nB0; zB1 = nB1; zB2 = nB2; zB3 = nB3;
        __syncthreads();
    }
}

// ---------------- dense head + softmax -------------------------------------
__global__ void head_kernel(const float* __restrict__ h2, const float* __restrict__ Wd,
                            const float* __restrict__ bd, float* __restrict__ out)
{
    __shared__ float hsh[H2D];
    const int b = blockIdx.x;
    const int lane = threadIdx.x;
    for (int j = lane; j < H2D; j += 32) hsh[j] = h2[b * H2D + j];
    __syncthreads();

    float acc = 0.f;
    if (lane < NC) {
        acc = bd[lane];
#pragma unroll
        for (int j = 0; j < H2D; ++j) acc = fmaf(hsh[j], Wd[j * NC + lane], acc);
    }
    float v = (lane < NC) ? acc : -FLT_MAX;
#pragma unroll
    for (int off = 16; off > 0; off >>= 1)
        v = fmaxf(v, __shfl_xor_sync(0xffffffffu, v, off));
    float e = (lane < NC) ? expf(acc - v) : 0.f;
    float s = e;
#pragma unroll
    for (int off = 16; off > 0; off >>= 1)
        s += __shfl_xor_sync(0xffffffffu, s, off);
    if (lane < NC) out[b * NC + lane] = e / s;
}

// ---------------- launch ----------------------------------------------------
extern "C" void kernel_launch(void* const* d_in, const int* in_sizes, int n_in,
                              void* d_out, int out_size)
{
    const float* x  = (const float*)d_in[0];
    const float* W1 = (const float*)d_in[1];
    const float* U1 = (const float*)d_in[2];
    const float* b1 = (const float*)d_in[3];
    const float* W2 = (const float*)d_in[4];
    const float* U2 = (const float*)d_in[5];
    const float* b2 = (const float*)d_in[6];
    const float* Wd = (const float*)d_in[7];
    const float* bd = (const float*)d_in[8];
    float* out = (float*)d_out;

    const int gemm_smem  = KPMAX * APM * 8 + KPMAX * BN * 8;               // 66560
    const int scan1_smem = (512 * U1SMJ + 2 * 4 * H1P + 128 * ZSP) * 4;    // 54528
    const int scan2_smem = (512 * U2P + 2 * 4 * H2D + 128 * ZSP) * 4;      // 120832
    cudaFuncSetAttribute(gemm_ff,    cudaFuncAttributeMaxDynamicSharedMemorySize, gemm_smem);
    cudaFuncSetAttribute(lstm_scan1, cudaFuncAttributeMaxDynamicSharedMemorySize, scan1_smem);
    cudaFuncSetAttribute(lstm_scan2, cudaFuncAttributeMaxDynamicSharedMemorySize, scan2_smem);

    float *zx1p, *h1p, *zx2p, *h2p;
    cudaGetSymbolAddress((void**)&zx1p, g_zx1);
    cudaGetSymbolAddress((void**)&h1p,  g_h1);
    cudaGetSymbolAddress((void**)&zx2p, g_zx2);
    cudaGetSymbolAddress((void**)&h2p,  g_h2);

    const int M = T_SEQ * BATCH;

    gemm_ff<<<M / BM, 256, gemm_smem>>>(x, W1, b1, zx1p, M, G1D, IND, 1);

    lstm_scan1<<<BATCH / 4, 256, scan1_smem>>>(zx1p, U1, h1p);

    gemm_ff<<<M / BM, 256, gemm_smem>>>(h1p, W2, b2, zx2p, M, G2D, H1D, 0);

    lstm_scan2<<<BATCH / 4, 256, scan2_smem>>>(zx2p, U2, h2p);

    head_kernel<<<BATCH, 32>>>(h2p, Wd, bd, out);
}

// round 12
// speedup vs baseline: 1.1966x; 1.1675x over previous
#include <cuda_runtime.h>
#include <math.h>
#include <float.h>

// Problem dims
#define T_SEQ 256
#define BATCH 512
#define IND   128
#define H1D   100
#define G1D   400     // 4*H1
#define H2D   128
#define G2D   512     // 4*H2
#define NC    19

typedef unsigned long long u64;

__device__ __forceinline__ void ffma2(u64 &d, u64 a, u64 b) {
    asm("fma.rn.f32x2 %0, %1, %2, %0;" : "+l"(d) : "l"(a), "l"(b));
}
__device__ __forceinline__ u64 pack2(float x, float y) {
    u64 r; asm("mov.b64 %0, {%1, %2};" : "=l"(r) : "f"(x), "f"(y)); return r;
}
__device__ __forceinline__ float2 unpk(u64 v) {
    float2 r; asm("mov.b64 {%0, %1}, %2;" : "=f"(r.x), "=f"(r.y) : "l"(v)); return r;
}
__device__ __forceinline__ float fsig(float a) {
    return __fdividef(1.f, 1.f + __expf(-a));
}

// ---------------- scratch ---------------------------------------------------
__device__ float g_zx1[256u*512u*400u];   // [(t,b)][G1]
__device__ float g_h1 [256u*512u*100u];   // [(t,b)][H1]
__device__ float g_zx2[256u*512u*512u];   // [(t,b)][G2]
__device__ float g_h2 [512u*128u];        // [B][H2]

// ---------------- feedforward GEMM: k-pair packed, conflict-free split B ----
// f32x2 lanes = (even-k, odd-k) partials. B k-pairs stored owner-ordered in
// BsLo/BsHi so lane tx reads contiguous 16B -> zero bank conflicts (R9-style
// access pattern). Inner loop: 4 LDS.128 + 16 FFMA2 per k-pair, no packs.
#define BM 64
#define BN 64
#define KPMAX 64     // max k-pairs (K<=128)
#define APM 66       // As2 row stride in u64

__global__ __launch_bounds__(256, 3)
void gemm_ff(const float* __restrict__ A, const float* __restrict__ Bw,
             const float* __restrict__ bias, float* __restrict__ C,
             int M, int N, int K, int mode)
{
    extern __shared__ __align__(16) char smraw[];
    u64* As2  = reinterpret_cast<u64*>(smraw);     // [KPMAX][APM]
    u64* BsLo = As2 + KPMAX * APM;                 // [KPMAX][32]: cols 4q,4q+1   at [kk][2q..2q+1]
    u64* BsHi = BsLo + KPMAX * 32;                 // [KPMAX][32]: cols 4q+2,4q+3 at [kk][2q..2q+1]

    const int tid = threadIdx.x;
    const int m0 = blockIdx.x * BM;
    const int tx = tid & 15, ty = tid >> 4;
    const int kp = K >> 1;
    const int nf4 = K >> 2;

    // load A tile once: float4 LDG -> two u64 k-pair entries
    for (int idx = tid; idx < BM * nf4; idx += 256) {
        int mloc = idx / nf4;
        int f = idx - mloc * nf4;
        int m = m0 + mloc;
        size_t arow;
        if (mode) { int t = m >> 9; int b = m & 511; arow = ((size_t)(b * T_SEQ + t)) * IND; }
        else      { arow = (size_t)m * K; }
        float4 v = *reinterpret_cast<const float4*>(&A[arow + 4 * f]);
        As2[(2 * f + 0) * APM + mloc] = pack2(v.x, v.y);
        As2[(2 * f + 1) * APM + mloc] = pack2(v.z, v.w);
    }

    const int ntiles = (N + BN - 1) / BN;
    for (int nt = 0; nt < ntiles; ++nt) {
        const int n0 = nt * BN;
        if (nt > 0) __syncthreads();
        // load B chunk: column n -> owner-ordered slot
        for (int idx = tid; idx < kp * BN; idx += 256) {
            int kk = idx >> 6;
            int n = idx & 63;
            int gn = n0 + n;
            float b0 = 0.f, b1 = 0.f;
            if (gn < N) {
                b0 = Bw[(size_t)(2 * kk + 0) * N + gn];
                b1 = Bw[(size_t)(2 * kk + 1) * N + gn];
            }
            int q = n >> 2, r = n & 3;
            u64* dst = (r < 2) ? &BsLo[kk * 32 + 2 * q + r]
                               : &BsHi[kk * 32 + 2 * q + (r - 2)];
            *dst = pack2(b0, b1);
        }
        __syncthreads();

        u64 acc2[4][4];
#pragma unroll
        for (int i = 0; i < 4; i++)
#pragma unroll
            for (int j = 0; j < 4; j++) acc2[i][j] = 0ull;

#pragma unroll 4
        for (int kk = 0; kk < kp; ++kk) {
            ulonglong2 a01 = *reinterpret_cast<const ulonglong2*>(&As2[kk * APM + ty * 4]);
            ulonglong2 a23 = *reinterpret_cast<const ulonglong2*>(&As2[kk * APM + ty * 4 + 2]);
            ulonglong2 b01 = *reinterpret_cast<const ulonglong2*>(&BsLo[kk * 32 + 2 * tx]);
            ulonglong2 b23 = *reinterpret_cast<const ulonglong2*>(&BsHi[kk * 32 + 2 * tx]);
            // b01 = (col 4tx, col 4tx+1), b23 = (col 4tx+2, col 4tx+3)
            ffma2(acc2[0][0], a01.x, b01.x); ffma2(acc2[0][1], a01.x, b01.y);
            ffma2(acc2[0][2], a01.x, b23.x); ffma2(acc2[0][3], a01.x, b23.y);
            ffma2(acc2[1][0], a01.y, b01.x); ffma2(acc2[1][1], a01.y, b01.y);
            ffma2(acc2[1][2], a01.y, b23.x); ffma2(acc2[1][3], a01.y, b23.y);
            ffma2(acc2[2][0], a23.x, b01.x); ffma2(acc2[2][1], a23.x, b01.y);
            ffma2(acc2[2][2], a23.x, b23.x); ffma2(acc2[2][3], a23.x, b23.y);
            ffma2(acc2[3][0], a23.y, b01.x); ffma2(acc2[3][1], a23.y, b01.y);
            ffma2(acc2[3][2], a23.y, b23.x); ffma2(acc2[3][3], a23.y, b23.y);
        }

        const int n = n0 + tx * 4;
#pragma unroll
        for (int i = 0; i < 4; i++) {
            int m = m0 + ty * 4 + i;
            float2 c0 = unpk(acc2[i][0]);
            float2 c1 = unpk(acc2[i][1]);
            float2 c2 = unpk(acc2[i][2]);
            float2 c3 = unpk(acc2[i][3]);
            float* cp = &C[(size_t)m * N + n];
            if (n + 3 < N) {
                float4 v;
                v.x = c0.x + c0.y + bias[n + 0];
                v.y = c1.x + c1.y + bias[n + 1];
                v.z = c2.x + c2.y + bias[n + 2];
                v.w = c3.x + c3.y + bias[n + 3];
                *reinterpret_cast<float4*>(cp) = v;
            } else {
                float vv[4] = {c0.x + c0.y, c1.x + c1.y, c2.x + c2.y, c3.x + c3.y};
#pragma unroll
                for (int jj = 0; jj < 4; jj++)
                    if (n + jj < N) cp[jj] = vv[jj] + bias[n + jj];
            }
        }
    }
}

// ---------------- layer-1 scan: 256 threads, 2 columns/thread (R7) ----------
#define U1REGJ 80
#define U1SMJ  20
#define H1P    104
#define ZSP    20
__global__ __launch_bounds__(256, 1)
void lstm_scan1(const float* __restrict__ zx, const float* __restrict__ U,
                float* __restrict__ hout)
{
    extern __shared__ __align__(16) float sm1[];
    float* U1sT = sm1;                       // [512 slots][U1SMJ]
    float* hT   = sm1 + 512 * U1SMJ;         // [2][4][H1P]
    float* zs   = hT + 2 * 4 * H1P;          // [128][ZSP]

    const int tid = threadIdx.x;
    const int j4 = tid >> 2;                 // 0..63
    const int k  = tid & 3;
    const int jA = (j4 < 50) ? j4 : 49;
    const int jB = jA + 50;
    const int colA = k * H1D + jA;
    const int colB = k * H1D + jB;
    const int b0 = blockIdx.x * 4;

    u64 UpA[U1REGJ / 2], UpB[U1REGJ / 2];
#pragma unroll
    for (int p = 0; p < U1REGJ / 2; ++p) {
        UpA[p] = pack2(U[(2 * p) * G1D + colA], U[(2 * p + 1) * G1D + colA]);
        UpB[p] = pack2(U[(2 * p) * G1D + colB], U[(2 * p + 1) * G1D + colB]);
    }
#pragma unroll
    for (int jj = 0; jj < U1SMJ; ++jj) {
        U1sT[tid * U1SMJ + jj]         = U[(U1REGJ + jj) * G1D + colA];
        U1sT[(256 + tid) * U1SMJ + jj] = U[(U1REGJ + jj) * G1D + colB];
    }
    for (int i = tid; i < 2 * 4 * H1P; i += 256) hT[i] = 0.f;

    float cA = 0.f, cB = 0.f;
    const float* zbA = zx + colA;
    const float* zbB = zx + colB;
    float zA0 = zbA[((size_t)0 * BATCH + b0 + 0) * G1D];
    float zA1 = zbA[((size_t)0 * BATCH + b0 + 1) * G1D];
    float zA2 = zbA[((size_t)0 * BATCH + b0 + 2) * G1D];
    float zA3 = zbA[((size_t)0 * BATCH + b0 + 3) * G1D];
    float zB0 = zbB[((size_t)0 * BATCH + b0 + 0) * G1D];
    float zB1 = zbB[((size_t)0 * BATCH + b0 + 1) * G1D];
    float zB2 = zbB[((size_t)0 * BATCH + b0 + 2) * G1D];
    float zB3 = zbB[((size_t)0 * BATCH + b0 + 3) * G1D];
    __syncthreads();

#pragma unroll 1
    for (int t = 0; t < T_SEQ; ++t) {
        int tn = (t + 1 < T_SEQ) ? (t + 1) : t;
        float nA0 = zbA[((size_t)tn * BATCH + b0 + 0) * G1D];
        float nA1 = zbA[((size_t)tn * BATCH + b0 + 1) * G1D];
        float nA2 = zbA[((size_t)tn * BATCH + b0 + 2) * G1D];
        float nA3 = zbA[((size_t)tn * BATCH + b0 + 3) * G1D];
        float nB0 = zbB[((size_t)tn * BATCH + b0 + 0) * G1D];
        float nB1 = zbB[((size_t)tn * BATCH + b0 + 1) * G1D];
        float nB2 = zbB[((size_t)tn * BATCH + b0 + 2) * G1D];
        float nB3 = zbB[((size_t)tn * BATCH + b0 + 3) * G1D];

        const float* hp = hT + (t & 1) * (4 * H1P);
        u64 aA0 = 0ull, aA1 = 0ull, aA2 = 0ull, aA3 = 0ull;
        u64 aB0 = 0ull, aB1 = 0ull, aB2 = 0ull, aB3 = 0ull;
#pragma unroll
        for (int p4 = 0; p4 < U1REGJ / 4; ++p4) {
            int j0 = 4 * p4;
            ulonglong2 h0 = *reinterpret_cast<const ulonglong2*>(&hp[0 * H1P + j0]);
            ulonglong2 h1 = *reinterpret_cast<const ulonglong2*>(&hp[1 * H1P + j0]);
            ulonglong2 h2 = *reinterpret_cast<const ulonglong2*>(&hp[2 * H1P + j0]);
            ulonglong2 h3 = *reinterpret_cast<const ulonglong2*>(&hp[3 * H1P + j0]);
            u64 ua = UpA[2 * p4], ub = UpA[2 * p4 + 1];
            u64 va = UpB[2 * p4], vb = UpB[2 * p4 + 1];
            ffma2(aA0, h0.x, ua); ffma2(aA0, h0.y, ub);
            ffma2(aA1, h1.x, ua); ffma2(aA1, h1.y, ub);
            ffma2(aA2, h2.x, ua); ffma2(aA2, h2.y, ub);
            ffma2(aA3, h3.x, ua); ffma2(aA3, h3.y, ub);
            ffma2(aB0, h0.x, va); ffma2(aB0, h0.y, vb);
            ffma2(aB1, h1.x, va); ffma2(aB1, h1.y, vb);
            ffma2(aB2, h2.x, va); ffma2(aB2, h2.y, vb);
            ffma2(aB3, h3.x, va); ffma2(aB3, h3.y, vb);
        }
#pragma unroll
        for (int q = 0; q < U1SMJ / 4; ++q) {
            int j0 = U1REGJ + 4 * q;
            ulonglong2 uA = *reinterpret_cast<const ulonglong2*>(&U1sT[tid * U1SMJ + 4 * q]);
            ulonglong2 uB = *reinterpret_cast<const ulonglong2*>(&U1sT[(256 + tid) * U1SMJ + 4 * q]);
            ulonglong2 h0 = *reinterpret_cast<const ulonglong2*>(&hp[0 * H1P + j0]);
            ulonglong2 h1 = *reinterpret_cast<const ulonglong2*>(&hp[1 * H1P + j0]);
            ulonglong2 h2 = *reinterpret_cast<const ulonglong2*>(&hp[2 * H1P + j0]);
            ulonglong2 h3 = *reinterpret_cast<const ulonglong2*>(&hp[3 * H1P + j0]);
            ffma2(aA0, h0.x, uA.x); ffma2(aA0, h0.y, uA.y);
            ffma2(aA1, h1.x, uA.x); ffma2(aA1, h1.y, uA.y);
            ffma2(aA2, h2.x, uA.x); ffma2(aA2, h2.y, uA.y);
            ffma2(aA3, h3.x, uA.x); ffma2(aA3, h3.y, uA.y);
            ffma2(aB0, h0.x, uB.x); ffma2(aB0, h0.y, uB.y);
            ffma2(aB1, h1.x, uB.x); ffma2(aB1, h1.y, uB.y);
            ffma2(aB2, h2.x, uB.x); ffma2(aB2, h2.y, uB.y);
            ffma2(aB3, h3.x, uB.x); ffma2(aB3, h3.y, uB.y);
        }
        float2 sA0 = unpk(aA0), sA1 = unpk(aA1), sA2 = unpk(aA2), sA3 = unpk(aA3);
        float2 sB0 = unpk(aB0), sB1 = unpk(aB1), sB2 = unpk(aB2), sB3 = unpk(aB3);
        float vA0 = sA0.x + sA0.y + zA0;
        float vA1 = sA1.x + sA1.y + zA1;
        float vA2 = sA2.x + sA2.y + zA2;
        float vA3 = sA3.x + sA3.y + zA3;
        float vB0 = sB0.x + sB0.y + zB0;
        float vB1 = sB1.x + sB1.y + zB1;
        float vB2 = sB2.x + sB2.y + zB2;
        float vB3 = sB3.x + sB3.y + zB3;
        if (k == 2) {
            vA0 = fmaxf(vA0, 0.f); vA1 = fmaxf(vA1, 0.f);
            vA2 = fmaxf(vA2, 0.f); vA3 = fmaxf(vA3, 0.f);
            vB0 = fmaxf(vB0, 0.f); vB1 = fmaxf(vB1, 0.f);
            vB2 = fmaxf(vB2, 0.f); vB3 = fmaxf(vB3, 0.f);
        } else {
            vA0 = fsig(vA0); vA1 = fsig(vA1); vA2 = fsig(vA2); vA3 = fsig(vA3);
            vB0 = fsig(vB0); vB1 = fsig(vB1); vB2 = fsig(vB2); vB3 = fsig(vB3);
        }
        *reinterpret_cast<float4*>(&zs[jA * ZSP + k * 4]) = make_float4(vA0, vA1, vA2, vA3);
        *reinterpret_cast<float4*>(&zs[jB * ZSP + k * 4]) = make_float4(vB0, vB1, vB2, vB3);
        __syncwarp();
        {
            float gi = zs[jA * ZSP + 0  + k];
            float gf = zs[jA * ZSP + 4  + k];
            float gg = zs[jA * ZSP + 8  + k];
            float go = zs[jA * ZSP + 12 + k];
            cA = fmaf(gf, cA, gi * gg);
            float h = go * fmaxf(cA, 0.f);
            hT[(1 - (t & 1)) * (4 * H1P) + k * H1P + jA] = h;
            if (j4 < 50) hout[((size_t)t * BATCH + b0 + k) * H1D + jA] = h;
        }
        {
            float gi = zs[jB * ZSP + 0  + k];
            float gf = zs[jB * ZSP + 4  + k];
            float gg = zs[jB * ZSP + 8  + k];
            float go = zs[jB * ZSP + 12 + k];
            cB = fmaf(gf, cB, gi * gg);
            float h = go * fmaxf(cB, 0.f);
            hT[(1 - (t & 1)) * (4 * H1P) + k * H1P + jB] = h;
            if (j4 < 50) hout[((size_t)t * BATCH + b0 + k) * H1D + jB] = h;
        }
        zA0 = nA0; zA1 = nA1; zA2 = nA2; zA3 = nA3;
        zB0 = nB0; zB1 = nB1; zB2 = nB2; zB3 = nB3;
        __syncthreads();
    }
}

// ---------------- layer-2 scan (R6-proven): 256 threads, 2 cols/thread ------
#define U2REGJ 80
#define U2SMJ  48
#define U2P    52
__global__ __launch_bounds__(256, 1)
void lstm_scan2(const float* __restrict__ zx, const float* __restrict__ U,
                float* __restrict__ h2out)
{
    extern __shared__ __align__(16) float sm2[];
    float* U2sT = sm2;                       // [512 slots][U2P]
    float* hT   = sm2 + 512 * U2P;           // [2][4][H2D]
    float* zs   = hT + 2 * 4 * H2D;          // [128][ZSP]

    const int tid = threadIdx.x;
    const int j  = tid >> 2;        // 0..63
    const int k  = tid & 3;
    const int jA = j, jB = j + 64;
    const int colA = k * H2D + jA;
    const int colB = k * H2D + jB;
    const int b0 = blockIdx.x * 4;

    u64 UpA[U2REGJ / 2], UpB[U2REGJ / 2];
#pragma unroll
    for (int p = 0; p < U2REGJ / 2; ++p) {
        UpA[p] = pack2(U[(2 * p) * G2D + colA], U[(2 * p + 1) * G2D + colA]);
        UpB[p] = pack2(U[(2 * p) * G2D + colB], U[(2 * p + 1) * G2D + colB]);
    }
    for (int idx = tid; idx < U2SMJ * G2D; idx += 256) {
        int r = idx >> 9;
        int cc = idx & 511;
        int jj = cc & 127, kk = cc >> 7;
        int slot = (jj < 64) ? (4 * jj + kk) : (256 + 4 * (jj - 64) + kk);
        U2sT[slot * U2P + r] = U[(size_t)(U2REGJ + r) * G2D + cc];
    }
    for (int i = tid; i < 2 * 4 * H2D; i += 256) hT[i] = 0.f;

    float cA = 0.f, cB = 0.f;
    const float* zbA = zx + colA;
    const float* zbB = zx + colB;
    float zA0 = zbA[((size_t)0 * BATCH + b0 + 0) * G2D];
    float zA1 = zbA[((size_t)0 * BATCH + b0 + 1) * G2D];
    float zA2 = zbA[((size_t)0 * BATCH + b0 + 2) * G2D];
    float zA3 = zbA[((size_t)0 * BATCH + b0 + 3) * G2D];
    float zB0 = zbB[((size_t)0 * BATCH + b0 + 0) * G2D];
    float zB1 = zbB[((size_t)0 * BATCH + b0 + 1) * G2D];
    float zB2 = zbB[((size_t)0 * BATCH + b0 + 2) * G2D];
    float zB3 = zbB[((size_t)0 * BATCH + b0 + 3) * G2D];
    __syncthreads();

#pragma unroll 1
    for (int t = 0; t < T_SEQ; ++t) {
        int tn = (t + 1 < T_SEQ) ? (t + 1) : t;
        float nA0 = zbA[((size_t)tn * BATCH + b0 + 0) * G2D];
        float nA1 = zbA[((size_t)tn * BATCH + b0 + 1) * G2D];
        float nA2 = zbA[((size_t)tn * BATCH + b0 + 2) * G2D];
        float nA3 = zbA[((size_t)tn * BATCH + b0 + 3) * G2D];
        float nB0 = zbB[((size_t)tn * BATCH + b0 + 0) * G2D];
        float nB1 = zbB[((size_t)tn * BATCH + b0 + 1) * G2D];
        float nB2 = zbB[((size_t)tn * BATCH + b0 + 2) * G2D];
        float nB3 = zbB[((size_t)tn * BATCH + b0 + 3) * G2D];

        const float* hp = hT + (t & 1) * (4 * H2D);
        u64 aA0 = 0ull, aA1 = 0ull, aA2 = 0ull, aA3 = 0ull;
        u64 aB0 = 0ull, aB1 = 0ull, aB2 = 0ull, aB3 = 0ull;
#pragma unroll
        for (int p4 = 0; p4 < U2REGJ / 4; ++p4) {
            int j0 = 4 * p4;
            ulonglong2 h0 = *reinterpret_cast<const ulonglong2*>(&hp[0 * H2D + j0]);
            ulonglong2 h1 = *reinterpret_cast<const ulonglong2*>(&hp[1 * H2D + j0]);
            ulonglong2 h2 = *reinterpret_cast<const ulonglong2*>(&hp[2 * H2D + j0]);
            ulonglong2 h3 = *reinterpret_cast<const ulonglong2*>(&hp[3 * H2D + j0]);
            u64 ua = UpA[2 * p4], ub = UpA[2 * p4 + 1];
            u64 va = UpB[2 * p4], vb = UpB[2 * p4 + 1];
            ffma2(aA0, h0.x, ua); ffma2(aA0, h0.y, ub);
            ffma2(aA1, h1.x, ua); ffma2(aA1, h1.y, ub);
            ffma2(aA2, h2.x, ua); ffma2(aA2, h2.y, ub);
            ffma2(aA3, h3.x, ua); ffma2(aA3, h3.y, ub);
            ffma2(aB0, h0.x, va); ffma2(aB0, h0.y, vb);
            ffma2(aB1, h1.x, va); ffma2(aB1, h1.y, vb);
            ffma2(aB2, h2.x, va); ffma2(aB2, h2.y, vb);
            ffma2(aB3, h3.x, va); ffma2(aB3, h3.y, vb);
        }
#pragma unroll
        for (int q = 0; q < U2SMJ / 4; ++q) {
            int j0 = U2REGJ + 4 * q;
            ulonglong2 uA = *reinterpret_cast<const ulonglong2*>(&U2sT[tid * U2P + 4 * q]);
            ulonglong2 uB = *reinterpret_cast<const ulonglong2*>(&U2sT[(256 + tid) * U2P + 4 * q]);
            ulonglong2 h0 = *reinterpret_cast<const ulonglong2*>(&hp[0 * H2D + j0]);
            ulonglong2 h1 = *reinterpret_cast<const ulonglong2*>(&hp[1 * H2D + j0]);
            ulonglong2 h2 = *reinterpret_cast<const ulonglong2*>(&hp[2 * H2D + j0]);
            ulonglong2 h3 = *reinterpret_cast<const ulonglong2*>(&hp[3 * H2D + j0]);
            ffma2(aA0, h0.x, uA.x); ffma2(aA0, h0.y, uA.y);
            ffma2(aA1, h1.x, uA.x); ffma2(aA1, h1.y, uA.y);
            ffma2(aA2, h2.x, uA.x); ffma2(aA2, h2.y, uA.y);
            ffma2(aA3, h3.x, uA.x); ffma2(aA3, h3.y, uA.y);
            ffma2(aB0, h0.x, uB.x); ffma2(aB0, h0.y, uB.y);
            ffma2(aB1, h1.x, uB.x); ffma2(aB1, h1.y, uB.y);
            ffma2(aB2, h2.x, uB.x); ffma2(aB2, h2.y, uB.y);
            ffma2(aB3, h3.x, uB.x); ffma2(aB3, h3.y, uB.y);
        }
        float2 sA0 = unpk(aA0), sA1 = unpk(aA1), sA2 = unpk(aA2), sA3 = unpk(aA3);
        float2 sB0 = unpk(aB0), sB1 = unpk(aB1), sB2 = unpk(aB2), sB3 = unpk(aB3);
        float vA0 = sA0.x + sA0.y + zA0;
        float vA1 = sA1.x + sA1.y + zA1;
        float vA2 = sA2.x + sA2.y + zA2;
        float vA3 = sA3.x + sA3.y + zA3;
        float vB0 = sB0.x + sB0.y + zB0;
        float vB1 = sB1.x + sB1.y + zB1;
        float vB2 = sB2.x + sB2.y + zB2;
        float vB3 = sB3.x + sB3.y + zB3;
        if (k == 2) {
            vA0 = fmaxf(vA0, 0.f); vA1 = fmaxf(vA1, 0.f);
            vA2 = fmaxf(vA2, 0.f); vA3 = fmaxf(vA3, 0.f);
            vB0 = fmaxf(vB0, 0.f); vB1 = fmaxf(vB1, 0.f);
            vB2 = fmaxf(vB2, 0.f); vB3 = fmaxf(vB3, 0.f);
        } else {
            vA0 = fsig(vA0); vA1 = fsig(vA1); vA2 = fsig(vA2); vA3 = fsig(vA3);
            vB0 = fsig(vB0); vB1 = fsig(vB1); vB2 = fsig(vB2); vB3 = fsig(vB3);
        }
        *reinterpret_cast<float4*>(&zs[jA * ZSP + k * 4]) = make_float4(vA0, vA1, vA2, vA3);
        *reinterpret_cast<float4*>(&zs[jB * ZSP + k * 4]) = make_float4(vB0, vB1, vB2, vB3);
        __syncwarp();
        {
            float gi = zs[jA * ZSP + 0  + k];
            float gf = zs[jA * ZSP + 4  + k];
            float gg = zs[jA * ZSP + 8  + k];
            float go = zs[jA * ZSP + 12 + k];
            cA = fmaf(gf, cA, gi * gg);
            float h = go * fmaxf(cA, 0.f);
            hT[(1 - (t & 1)) * (4 * H2D) + k * H2D + jA] = h;
            if (t == T_SEQ - 1) h2out[(b0 + k) * H2D + jA] = h;
        }
        {
            float gi = zs[jB * ZSP + 0  + k];
            float gf = zs[jB * ZSP + 4  + k];
            float gg = zs[jB * ZSP + 8  + k];
            float go = zs[jB * ZSP + 12 + k];
            cB = fmaf(gf, cB, gi * gg);
            float h = go * fmaxf(cB, 0.f);
            hT[(1 - (t & 1)) * (4 * H2D) + k * H2D + jB] = h;
            if (t == T_SEQ - 1) h2out[(b0 + k) * H2D + jB] = h;
        }
        zA0 = nA0; zA1 = nA1; zA2 = nA2; zA3 = nA3;
        zB0 = nB0; zB1 = nB1; zB2 = nB2; zB3 = nB3;
        __syncthreads();
    }
}

// ---------------- dense head + softmax -------------------------------------
__global__ void head_kernel(const float* __restrict__ h2, const float* __restrict__ Wd,
                            const float* __restrict__ bd, float* __restrict__ out)
{
    __shared__ float hsh[H2D];
    const int b = blockIdx.x;
    const int lane = threadIdx.x;
    for (int j = lane; j < H2D; j += 32) hsh[j] = h2[b * H2D + j];
    __syncthreads();

    float acc = 0.f;
    if (lane < NC) {
        acc = bd[lane];
#pragma unroll
        for (int j = 0; j < H2D; ++j) acc = fmaf(hsh[j], Wd[j * NC + lane], acc);
    }
    float v = (lane < NC) ? acc : -FLT_MAX;
#pragma unroll
    for (int off = 16; off > 0; off >>= 1)
        v = fmaxf(v, __shfl_xor_sync(0xffffffffu, v, off));
    float e = (lane < NC) ? expf(acc - v) : 0.f;
    float s = e;
#pragma unroll
    for (int off = 16; off > 0; off >>= 1)
        s += __shfl_xor_sync(0xffffffffu, s, off);
    if (lane < NC) out[b * NC + lane] = e / s;
}

// ---------------- launch ----------------------------------------------------
extern "C" void kernel_launch(void* const* d_in, const int* in_sizes, int n_in,
                              void* d_out, int out_size)
{
    const float* x  = (const float*)d_in[0];
    const float* W1 = (const float*)d_in[1];
    const float* U1 = (const float*)d_in[2];
    const float* b1 = (const float*)d_in[3];
    const float* W2 = (const float*)d_in[4];
    const float* U2 = (const float*)d_in[5];
    const float* b2 = (const float*)d_in[6];
    const float* Wd = (const float*)d_in[7];
    const float* bd = (const float*)d_in[8];
    float* out = (float*)d_out;

    const int gemm_smem  = KPMAX * APM * 8 + KPMAX * 64 * 8;               // 66560
    const int scan1_smem = (512 * U1SMJ + 2 * 4 * H1P + 128 * ZSP) * 4;    // 54528
    const int scan2_smem = (512 * U2P + 2 * 4 * H2D + 128 * ZSP) * 4;      // 120832
    cudaFuncSetAttribute(gemm_ff,    cudaFuncAttributeMaxDynamicSharedMemorySize, gemm_smem);
    cudaFuncSetAttribute(lstm_scan1, cudaFuncAttributeMaxDynamicSharedMemorySize, scan1_smem);
    cudaFuncSetAttribute(lstm_scan2, cudaFuncAttributeMaxDynamicSharedMemorySize, scan2_smem);

    float *zx1p, *h1p, *zx2p, *h2p;
    cudaGetSymbolAddress((void**)&zx1p, g_zx1);
    cudaGetSymbolAddress((void**)&h1p,  g_h1);
    cudaGetSymbolAddress((void**)&zx2p, g_zx2);
    cudaGetSymbolAddress((void**)&h2p,  g_h2);

    const int M = T_SEQ * BATCH;

    gemm_ff<<<M / BM, 256, gemm_smem>>>(x, W1, b1, zx1p, M, G1D, IND, 1);

    lstm_scan1<<<BATCH / 4, 256, scan1_smem>>>(zx1p, U1, h1p);

    gemm_ff<<<M / BM, 256, gemm_smem>>>(h1p, W2, b2, zx2p, M, G2D, H1D, 0);

    lstm_scan2<<<BATCH / 4, 256, scan2_smem>>>(zx2p, U2, h2p);

    head_kernel<<<BATCH, 32>>>(h2p, Wd, bd, out);
}

// round 13
// speedup vs baseline: 1.2299x; 1.0278x over previous
#include <cuda_runtime.h>
#include <math.h>
#include <float.h>

// Problem dims
#define T_SEQ 256
#define BATCH 512
#define IND   128
#define H1D   100
#define G1D   400     // 4*H1
#define H2D   128
#define G2D   512     // 4*H2
#define NC    19

typedef unsigned long long u64;

__device__ __forceinline__ void ffma2(u64 &d, u64 a, u64 b) {
    asm("fma.rn.f32x2 %0, %1, %2, %0;" : "+l"(d) : "l"(a), "l"(b));
}
__device__ __forceinline__ u64 pack2(float x, float y) {
    u64 r; asm("mov.b64 %0, {%1, %2};" : "=l"(r) : "f"(x), "f"(y)); return r;
}
__device__ __forceinline__ float2 unpk(u64 v) {
    float2 r; asm("mov.b64 {%0, %1}, %2;" : "=f"(r.x), "=f"(r.y) : "l"(v)); return r;
}
__device__ __forceinline__ float fsig(float a) {
    return __fdividef(1.f, 1.f + __expf(-a));
}

// 4x4 transpose within a lane quad (lanes 4j..4j+3), 2-phase butterfly.
// In: a_m = this gate's value for batch row m. Out: a_m = gate-m value for row k.
__device__ __forceinline__ void quad_transpose(float &a0, float &a1, float &a2,
                                               float &a3, int k) {
    float s, r;
    s = (k & 1) ? a0 : a1; r = __shfl_xor_sync(0xffffffffu, s, 1);
    if (k & 1) a0 = r; else a1 = r;
    s = (k & 1) ? a2 : a3; r = __shfl_xor_sync(0xffffffffu, s, 1);
    if (k & 1) a2 = r; else a3 = r;
    s = (k & 2) ? a0 : a2; r = __shfl_xor_sync(0xffffffffu, s, 2);
    if (k & 2) a0 = r; else a2 = r;
    s = (k & 2) ? a1 : a3; r = __shfl_xor_sync(0xffffffffu, s, 2);
    if (k & 2) a1 = r; else a3 = r;
}

// ---------------- scratch ---------------------------------------------------
__device__ float g_zx1[256u*512u*400u];   // [(t,b)][G1]
__device__ float g_h1 [256u*512u*100u];   // [(t,b)][H1]
__device__ float g_zx2[256u*512u*512u];   // [(t,b)][G2]
__device__ float g_h2 [512u*128u];        // [B][H2]

// ---------------- feedforward GEMM (R9-proven): A-resident n-loop -----------
#define BM 64
#define BN 64
#define KMAX 128
#define AP 68

__global__ __launch_bounds__(256, 3)
void gemm_ff(const float* __restrict__ A, const float* __restrict__ Bw,
             const float* __restrict__ bias, float* __restrict__ C,
             int M, int N, int K, int mode)
{
    extern __shared__ float sm[];
    float* As = sm;                 // [KMAX][AP]  transposed A tile
    float* Bs = sm + KMAX * AP;     // [KMAX][BN]

    const int tid = threadIdx.x;
    const int m0 = blockIdx.x * BM;
    const int tx = tid & 15, ty = tid >> 4;

    // load A tile once
    for (int idx = tid; idx < BM * K; idx += 256) {
        int mloc = idx / K;
        int k = idx - mloc * K;
        int m = m0 + mloc;
        size_t arow;
        if (mode) { int t = m >> 9; int b = m & 511; arow = ((size_t)(b * T_SEQ + t)) * IND; }
        else      { arow = (size_t)m * K; }
        As[k * AP + mloc] = A[arow + k];
    }

    const int ntiles = (N + BN - 1) / BN;
    for (int nt = 0; nt < ntiles; ++nt) {
        const int n0 = nt * BN;
        if (nt > 0) __syncthreads();
        for (int idx = tid; idx < K * BN; idx += 256) {
            int k = idx >> 6;
            int n = idx & 63;
            int gn = n0 + n;
            Bs[k * BN + n] = (gn < N) ? Bw[(size_t)k * N + gn] : 0.f;
        }
        __syncthreads();

        u64 acc2[2][4];
#pragma unroll
        for (int i = 0; i < 2; i++)
#pragma unroll
            for (int j = 0; j < 4; j++) acc2[i][j] = 0ull;

#pragma unroll 4
        for (int k = 0; k < K; ++k) {
            ulonglong2 av = *reinterpret_cast<const ulonglong2*>(&As[k * AP + ty * 4]);
            float4 bv = *reinterpret_cast<const float4*>(&Bs[k * BN + tx * 4]);
            u64 b0 = pack2(bv.x, bv.x);
            u64 b1 = pack2(bv.y, bv.y);
            u64 b2 = pack2(bv.z, bv.z);
            u64 b3 = pack2(bv.w, bv.w);
            ffma2(acc2[0][0], av.x, b0); ffma2(acc2[0][1], av.x, b1);
            ffma2(acc2[0][2], av.x, b2); ffma2(acc2[0][3], av.x, b3);
            ffma2(acc2[1][0], av.y, b0); ffma2(acc2[1][1], av.y, b1);
            ffma2(acc2[1][2], av.y, b2); ffma2(acc2[1][3], av.y, b3);
        }

        float accf[4][4];
#pragma unroll
        for (int j = 0; j < 4; j++) {
            float2 p = unpk(acc2[0][j]);
            float2 q = unpk(acc2[1][j]);
            accf[0][j] = p.x; accf[1][j] = p.y;
            accf[2][j] = q.x; accf[3][j] = q.y;
        }

#pragma unroll
        for (int i = 0; i < 4; i++) {
            int m = m0 + ty * 4 + i;
            int n = n0 + tx * 4;
            float* cp = &C[(size_t)m * N + n];
            if (n + 3 < N) {
                float4 v;
                v.x = accf[i][0] + bias[n + 0];
                v.y = accf[i][1] + bias[n + 1];
                v.z = accf[i][2] + bias[n + 2];
                v.w = accf[i][3] + bias[n + 3];
                *reinterpret_cast<float4*>(cp) = v;
            } else {
#pragma unroll
                for (int j = 0; j < 4; j++)
                    if (n + j < N) cp[j] = accf[i][j] + bias[n + j];
            }
        }
    }
}

// ---------------- layer-1 scan: 2 cols/thread + shfl gate exchange ----------
#define U1REGJ 80
#define U1SMJ  20
#define H1P    104
__global__ __launch_bounds__(256, 1)
void lstm_scan1(const float* __restrict__ zx, const float* __restrict__ U,
                float* __restrict__ hout)
{
    extern __shared__ __align__(16) float sm1[];
    float* U1sT = sm1;                       // [512 slots][U1SMJ]
    float* hT   = sm1 + 512 * U1SMJ;         // [2][4][H1P]

    const int tid = threadIdx.x;
    const int j4 = tid >> 2;                 // 0..63
    const int k  = tid & 3;
    const int jA = (j4 < 50) ? j4 : 49;
    const int jB = jA + 50;
    const int colA = k * H1D + jA;
    const int colB = k * H1D + jB;
    const int b0 = blockIdx.x * 4;

    u64 UpA[U1REGJ / 2], UpB[U1REGJ / 2];
#pragma unroll
    for (int p = 0; p < U1REGJ / 2; ++p) {
        UpA[p] = pack2(U[(2 * p) * G1D + colA], U[(2 * p + 1) * G1D + colA]);
        UpB[p] = pack2(U[(2 * p) * G1D + colB], U[(2 * p + 1) * G1D + colB]);
    }
#pragma unroll
    for (int jj = 0; jj < U1SMJ; ++jj) {
        U1sT[tid * U1SMJ + jj]         = U[(U1REGJ + jj) * G1D + colA];
        U1sT[(256 + tid) * U1SMJ + jj] = U[(U1REGJ + jj) * G1D + colB];
    }
    for (int i = tid; i < 2 * 4 * H1P; i += 256) hT[i] = 0.f;

    float cA = 0.f, cB = 0.f;
    const float* zbA = zx + colA;
    const float* zbB = zx + colB;
    float zA0 = zbA[((size_t)0 * BATCH + b0 + 0) * G1D];
    float zA1 = zbA[((size_t)0 * BATCH + b0 + 1) * G1D];
    float zA2 = zbA[((size_t)0 * BATCH + b0 + 2) * G1D];
    float zA3 = zbA[((size_t)0 * BATCH + b0 + 3) * G1D];
    float zB0 = zbB[((size_t)0 * BATCH + b0 + 0) * G1D];
    float zB1 = zbB[((size_t)0 * BATCH + b0 + 1) * G1D];
    float zB2 = zbB[((size_t)0 * BATCH + b0 + 2) * G1D];
    float zB3 = zbB[((size_t)0 * BATCH + b0 + 3) * G1D];
    __syncthreads();

#pragma unroll 1
    for (int t = 0; t < T_SEQ; ++t) {
        int tn = (t + 1 < T_SEQ) ? (t + 1) : t;
        float nA0 = zbA[((size_t)tn * BATCH + b0 + 0) * G1D];
        float nA1 = zbA[((size_t)tn * BATCH + b0 + 1) * G1D];
        float nA2 = zbA[((size_t)tn * BATCH + b0 + 2) * G1D];
        float nA3 = zbA[((size_t)tn * BATCH + b0 + 3) * G1D];
        float nB0 = zbB[((size_t)tn * BATCH + b0 + 0) * G1D];
        float nB1 = zbB[((size_t)tn * BATCH + b0 + 1) * G1D];
        float nB2 = zbB[((size_t)tn * BATCH + b0 + 2) * G1D];
        float nB3 = zbB[((size_t)tn * BATCH + b0 + 3) * G1D];

        const float* hp = hT + (t & 1) * (4 * H1P);
        u64 aA0 = 0ull, aA1 = 0ull, aA2 = 0ull, aA3 = 0ull;
        u64 aB0 = 0ull, aB1 = 0ull, aB2 = 0ull, aB3 = 0ull;
#pragma unroll
        for (int p4 = 0; p4 < U1REGJ / 4; ++p4) {
            int j0 = 4 * p4;
            ulonglong2 h0 = *reinterpret_cast<const ulonglong2*>(&hp[0 * H1P + j0]);
            ulonglong2 h1 = *reinterpret_cast<const ulonglong2*>(&hp[1 * H1P + j0]);
            ulonglong2 h2 = *reinterpret_cast<const ulonglong2*>(&hp[2 * H1P + j0]);
            ulonglong2 h3 = *reinterpret_cast<const ulonglong2*>(&hp[3 * H1P + j0]);
            u64 ua = UpA[2 * p4], ub = UpA[2 * p4 + 1];
            u64 va = UpB[2 * p4], vb = UpB[2 * p4 + 1];
            ffma2(aA0, h0.x, ua); ffma2(aA0, h0.y, ub);
            ffma2(aA1, h1.x, ua); ffma2(aA1, h1.y, ub);
            ffma2(aA2, h2.x, ua); ffma2(aA2, h2.y, ub);
            ffma2(aA3, h3.x, ua); ffma2(aA3, h3.y, ub);
            ffma2(aB0, h0.x, va); ffma2(aB0, h0.y, vb);
            ffma2(aB1, h1.x, va); ffma2(aB1, h1.y, vb);
            ffma2(aB2, h2.x, va); ffma2(aB2, h2.y, vb);
            ffma2(aB3, h3.x, va); ffma2(aB3, h3.y, vb);
        }
#pragma unroll
        for (int q = 0; q < U1SMJ / 4; ++q) {
            int j0 = U1REGJ + 4 * q;
            ulonglong2 uA = *reinterpret_cast<const ulonglong2*>(&U1sT[tid * U1SMJ + 4 * q]);
            ulonglong2 uB = *reinterpret_cast<const ulonglong2*>(&U1sT[(256 + tid) * U1SMJ + 4 * q]);
            ulonglong2 h0 = *reinterpret_cast<const ulonglong2*>(&hp[0 * H1P + j0]);
            ulonglong2 h1 = *reinterpret_cast<const ulonglong2*>(&hp[1 * H1P + j0]);
            ulonglong2 h2 = *reinterpret_cast<const ulonglong2*>(&hp[2 * H1P + j0]);
            ulonglong2 h3 = *reinterpret_cast<const ulonglong2*>(&hp[3 * H1P + j0]);
            ffma2(aA0, h0.x, uA.x); ffma2(aA0, h0.y, uA.y);
            ffma2(aA1, h1.x, uA.x); ffma2(aA1, h1.y, uA.y);
            ffma2(aA2, h2.x, uA.x); ffma2(aA2, h2.y, uA.y);
            ffma2(aA3, h3.x, uA.x); ffma2(aA3, h3.y, uA.y);
            ffma2(aB0, h0.x, uB.x); ffma2(aB0, h0.y, uB.y);
            ffma2(aB1, h1.x, uB.x); ffma2(aB1, h1.y, uB.y);
            ffma2(aB2, h2.x, uB.x); ffma2(aB2, h2.y, uB.y);
            ffma2(aB3, h3.x, uB.x); ffma2(aB3, h3.y, uB.y);
        }
        float2 sA0 = unpk(aA0), sA1 = unpk(aA1), sA2 = unpk(aA2), sA3 = unpk(aA3);
        float2 sB0 = unpk(aB0), sB1 = unpk(aB1), sB2 = unpk(aB2), sB3 = unpk(aB3);
        float vA0 = sA0.x + sA0.y + zA0;
        float vA1 = sA1.x + sA1.y + zA1;
        float vA2 = sA2.x + sA2.y + zA2;
        float vA3 = sA3.x + sA3.y + zA3;
        float vB0 = sB0.x + sB0.y + zB0;
        float vB1 = sB1.x + sB1.y + zB1;
        float vB2 = sB2.x + sB2.y + zB2;
        float vB3 = sB3.x + sB3.y + zB3;
        if (k == 2) {
            vA0 = fmaxf(vA0, 0.f); vA1 = fmaxf(vA1, 0.f);
            vA2 = fmaxf(vA2, 0.f); vA3 = fmaxf(vA3, 0.f);
            vB0 = fmaxf(vB0, 0.f); vB1 = fmaxf(vB1, 0.f);
            vB2 = fmaxf(vB2, 0.f); vB3 = fmaxf(vB3, 0.f);
        } else {
            vA0 = fsig(vA0); vA1 = fsig(vA1); vA2 = fsig(vA2); vA3 = fsig(vA3);
            vB0 = fsig(vB0); vB1 = fsig(vB1); vB2 = fsig(vB2); vB3 = fsig(vB3);
        }
        // warp-local 4x4 transpose: after, (vX0..vX3) = (gi,gf,gg,go) for row k
        quad_transpose(vA0, vA1, vA2, vA3, k);
        quad_transpose(vB0, vB1, vB2, vB3, k);
        {
            cA = fmaf(vA1, cA, vA0 * vA2);
            float h = vA3 * fmaxf(cA, 0.f);
            hT[(1 - (t & 1)) * (4 * H1P) + k * H1P + jA] = h;
            if (j4 < 50) hout[((size_t)t * BATCH + b0 + k) * H1D + jA] = h;
        }
        {
            cB = fmaf(vB1, cB, vB0 * vB2);
            float h = vB3 * fmaxf(cB, 0.f);
            hT[(1 - (t & 1)) * (4 * H1P) + k * H1P + jB] = h;
            if (j4 < 50) hout[((size_t)t * BATCH + b0 + k) * H1D + jB] = h;
        }
        zA0 = nA0; zA1 = nA1; zA2 = nA2; zA3 = nA3;
        zB0 = nB0; zB1 = nB1; zB2 = nB2; zB3 = nB3;
        __syncthreads();
    }
}

// ---------------- layer-2 scan: 2 cols/thread + shfl gate exchange ----------
#define U2REGJ 80
#define U2SMJ  48
#define U2P    52
__global__ __launch_bounds__(256, 1)
void lstm_scan2(const float* __restrict__ zx, const float* __restrict__ U,
                float* __restrict__ h2out)
{
    extern __shared__ __align__(16) float sm2[];
    float* U2sT = sm2;                       // [512 slots][U2P]
    float* hT   = sm2 + 512 * U2P;           // [2][4][H2D]

    const int tid = threadIdx.x;
    const int j  = tid >> 2;        // 0..63
    const int k  = tid & 3;
    const int jA = j, jB = j + 64;
    const int colA = k * H2D + jA;
    const int colB = k * H2D + jB;
    const int b0 = blockIdx.x * 4;

    u64 UpA[U2REGJ / 2], UpB[U2REGJ / 2];
#pragma unroll
    for (int p = 0; p < U2REGJ / 2; ++p) {
        UpA[p] = pack2(U[(2 * p) * G2D + colA], U[(2 * p + 1) * G2D + colA]);
        UpB[p] = pack2(U[(2 * p) * G2D + colB], U[(2 * p + 1) * G2D + colB]);
    }
    for (int idx = tid; idx < U2SMJ * G2D; idx += 256) {
        int r = idx >> 9;
        int cc = idx & 511;
        int jj = cc & 127, kk = cc >> 7;
        int slot = (jj < 64) ? (4 * jj + kk) : (256 + 4 * (jj - 64) + kk);
        U2sT[slot * U2P + r] = U[(size_t)(U2REGJ + r) * G2D + cc];
    }
    for (int i = tid; i < 2 * 4 * H2D; i += 256) hT[i] = 0.f;

    float cA = 0.f, cB = 0.f;
    const float* zbA = zx + colA;
    const float* zbB = zx + colB;
    float zA0 = zbA[((size_t)0 * BATCH + b0 + 0) * G2D];
    float zA1 = zbA[((size_t)0 * BATCH + b0 + 1) * G2D];
    float zA2 = zbA[((size_t)0 * BATCH + b0 + 2) * G2D];
    float zA3 = zbA[((size_t)0 * BATCH + b0 + 3) * G2D];
    float zB0 = zbB[((size_t)0 * BATCH + b0 + 0) * G2D];
    float zB1 = zbB[((size_t)0 * BATCH + b0 + 1) * G2D];
    float zB2 = zbB[((size_t)0 * BATCH + b0 + 2) * G2D];
    float zB3 = zbB[((size_t)0 * BATCH + b0 + 3) * G2D];
    __syncthreads();

#pragma unroll 1
    for (int t = 0; t < T_SEQ; ++t) {
        int tn = (t + 1 < T_SEQ) ? (t + 1) : t;
        float nA0 = zbA[((size_t)tn * BATCH + b0 + 0) * G2D];
        float nA1 = zbA[((size_t)tn * BATCH + b0 + 1) * G2D];
        float nA2 = zbA[((size_t)tn * BATCH + b0 + 2) * G2D];
        float nA3 = zbA[((size_t)tn * BATCH + b0 + 3) * G2D];
        float nB0 = zbB[((size_t)tn * BATCH + b0 + 0) * G2D];
        float nB1 = zbB[((size_t)tn * BATCH + b0 + 1) * G2D];
        float nB2 = zbB[((size_t)tn * BATCH + b0 + 2) * G2D];
        float nB3 = zbB[((size_t)tn * BATCH + b0 + 3) * G2D];

        const float* hp = hT + (t & 1) * (4 * H2D);
        u64 aA0 = 0ull, aA1 = 0ull, aA2 = 0ull, aA3 = 0ull;
        u64 aB0 = 0ull, aB1 = 0ull, aB2 = 0ull, aB3 = 0ull;
#pragma unroll
        for (int p4 = 0; p4 < U2REGJ / 4; ++p4) {
            int j0 = 4 * p4;
            ulonglong2 h0 = *reinterpret_cast<const ulonglong2*>(&hp[0 * H2D + j0]);
            ulonglong2 h1 = *reinterpret_cast<const ulonglong2*>(&hp[1 * H2D + j0]);
            ulonglong2 h2 = *reinterpret_cast<const ulonglong2*>(&hp[2 * H2D + j0]);
            ulonglong2 h3 = *reinterpret_cast<const ulonglong2*>(&hp[3 * H2D + j0]);
            u64 ua = UpA[2 * p4], ub = UpA[2 * p4 + 1];
            u64 va = UpB[2 * p4], vb = UpB[2 * p4 + 1];
            ffma2(aA0, h0.x, ua); ffma2(aA0, h0.y, ub);
            ffma2(aA1, h1.x, ua); ffma2(aA1, h1.y, ub);
            ffma2(aA2, h2.x, ua); ffma2(aA2, h2.y, ub);
            ffma2(aA3, h3.x, ua); ffma2(aA3, h3.y, ub);
            ffma2(aB0, h0.x, va); ffma2(aB0, h0.y, vb);
            ffma2(aB1, h1.x, va); ffma2(aB1, h1.y, vb);
            ffma2(aB2, h2.x, va); ffma2(aB2, h2.y, vb);
            ffma2(aB3, h3.x, va); ffma2(aB3, h3.y, vb);
        }
#pragma unroll
        for (int q = 0; q < U2SMJ / 4; ++q) {
            int j0 = U2REGJ + 4 * q;
            ulonglong2 uA = *reinterpret_cast<const ulonglong2*>(&U2sT[tid * U2P + 4 * q]);
            ulonglong2 uB = *reinterpret_cast<const ulonglong2*>(&U2sT[(256 + tid) * U2P + 4 * q]);
            ulonglong2 h0 = *reinterpret_cast<const ulonglong2*>(&hp[0 * H2D + j0]);
            ulonglong2 h1 = *reinterpret_cast<const ulonglong2*>(&hp[1 * H2D + j0]);
            ulonglong2 h2 = *reinterpret_cast<const ulonglong2*>(&hp[2 * H2D + j0]);
            ulonglong2 h3 = *reinterpret_cast<const ulonglong2*>(&hp[3 * H2D + j0]);
            ffma2(aA0, h0.x, uA.x); ffma2(aA0, h0.y, uA.y);
            ffma2(aA1, h1.x, uA.x); ffma2(aA1, h1.y, uA.y);
            ffma2(aA2, h2.x, uA.x); ffma2(aA2, h2.y, uA.y);
            ffma2(aA3, h3.x, uA.x); ffma2(aA3, h3.y, uA.y);
            ffma2(aB0, h0.x, uB.x); ffma2(aB0, h0.y, uB.y);
            ffma2(aB1, h1.x, uB.x); ffma2(aB1, h1.y, uB.y);
            ffma2(aB2, h2.x, uB.x); ffma2(aB2, h2.y, uB.y);
            ffma2(aB3, h3.x, uB.x); ffma2(aB3, h3.y, uB.y);
        }
        float2 sA0 = unpk(aA0), sA1 = unpk(aA1), sA2 = unpk(aA2), sA3 = unpk(aA3);
        float2 sB0 = unpk(aB0), sB1 = unpk(aB1), sB2 = unpk(aB2), sB3 = unpk(aB3);
        float vA0 = sA0.x + sA0.y + zA0;
        float vA1 = sA1.x + sA1.y + zA1;
        float vA2 = sA2.x + sA2.y + zA2;
        float vA3 = sA3.x + sA3.y + zA3;
        float vB0 = sB0.x + sB0.y + zB0;
        float vB1 = sB1.x + sB1.y + zB1;
        float vB2 = sB2.x + sB2.y + zB2;
        float vB3 = sB3.x + sB3.y + zB3;
        if (k == 2) {
            vA0 = fmaxf(vA0, 0.f); vA1 = fmaxf(vA1, 0.f);
            vA2 = fmaxf(vA2, 0.f); vA3 = fmaxf(vA3, 0.f);
            vB0 = fmaxf(vB0, 0.f); vB1 = fmaxf(vB1, 0.f);
            vB2 = fmaxf(vB2, 0.f); vB3 = fmaxf(vB3, 0.f);
        } else {
            vA0 = fsig(vA0); vA1 = fsig(vA1); vA2 = fsig(vA2); vA3 = fsig(vA3);
            vB0 = fsig(vB0); vB1 = fsig(vB1); vB2 = fsig(vB2); vB3 = fsig(vB3);
        }
        quad_transpose(vA0, vA1, vA2, vA3, k);
        quad_transpose(vB0, vB1, vB2, vB3, k);
        {
            cA = fmaf(vA1, cA, vA0 * vA2);
            float h = vA3 * fmaxf(cA, 0.f);
            hT[(1 - (t & 1)) * (4 * H2D) + k * H2D + jA] = h;
            if (t == T_SEQ - 1) h2out[(b0 + k) * H2D + jA] = h;
        }
        {
            cB = fmaf(vB1, cB, vB0 * vB2);
            float h = vB3 * fmaxf(cB, 0.f);
            hT[(1 - (t & 1)) * (4 * H2D) + k * H2D + jB] = h;
            if (t == T_SEQ - 1) h2out[(b0 + k) * H2D + jB] = h;
        }
        zA0 = nA0; zA1 = nA1; zA2 = nA2; zA3 = nA3;
        zB0 = nB0; zB1 = nB1; zB2 = nB2; zB3 = nB3;
        __syncthreads();
    }
}

// ---------------- dense head + softmax -------------------------------------
__global__ void head_kernel(const float* __restrict__ h2, const float* __restrict__ Wd,
                            const float* __restrict__ bd, float* __restrict__ out)
{
    __shared__ float hsh[H2D];
    const int b = blockIdx.x;
    const int lane = threadIdx.x;
    for (int j = lane; j < H2D; j += 32) hsh[j] = h2[b * H2D + j];
    __syncthreads();

    float acc = 0.f;
    if (lane < NC) {
        acc = bd[lane];
#pragma unroll
        for (int j = 0; j < H2D; ++j) acc = fmaf(hsh[j], Wd[j * NC + lane], acc);
    }
    float v = (lane < NC) ? acc : -FLT_MAX;
#pragma unroll
    for (int off = 16; off > 0; off >>= 1)
        v = fmaxf(v, __shfl_xor_sync(0xffffffffu, v, off));
    float e = (lane < NC) ? expf(acc - v) : 0.f;
    float s = e;
#pragma unroll
    for (int off = 16; off > 0; off >>= 1)
        s += __shfl_xor_sync(0xffffffffu, s, off);
    if (lane < NC) out[b * NC + lane] = e / s;
}

// ---------------- launch ----------------------------------------------------
extern "C" void kernel_launch(void* const* d_in, const int* in_sizes, int n_in,
                              void* d_out, int out_size)
{
    const float* x  = (const float*)d_in[0];
    const float* W1 = (const float*)d_in[1];
    const float* U1 = (const float*)d_in[2];
    const float* b1 = (const float*)d_in[3];
    const float* W2 = (const float*)d_in[4];
    const float* U2 = (const float*)d_in[5];
    const float* b2 = (const float*)d_in[6];
    const float* Wd = (const float*)d_in[7];
    const float* bd = (const float*)d_in[8];
    float* out = (float*)d_out;

    const int gemm_smem  = (KMAX * AP + KMAX * BN) * 4;                    // 67584
    const int scan1_smem = (512 * U1SMJ + 2 * 4 * H1P) * 4;                // 44288
    const int scan2_smem = (512 * U2P + 2 * 4 * H2D) * 4;                  // 110592
    cudaFuncSetAttribute(gemm_ff,    cudaFuncAttributeMaxDynamicSharedMemorySize, gemm_smem);
    cudaFuncSetAttribute(lstm_scan1, cudaFuncAttributeMaxDynamicSharedMemorySize, scan1_smem);
    cudaFuncSetAttribute(lstm_scan2, cudaFuncAttributeMaxDynamicSharedMemorySize, scan2_smem);

    float *zx1p, *h1p, *zx2p, *h2p;
    cudaGetSymbolAddress((void**)&zx1p, g_zx1);
    cudaGetSymbolAddress((void**)&h1p,  g_h1);
    cudaGetSymbolAddress((void**)&zx2p, g_zx2);
    cudaGetSymbolAddress((void**)&h2p,  g_h2);

    const int M = T_SEQ * BATCH;

    gemm_ff<<<M / BM, 256, gemm_smem>>>(x, W1, b1, zx1p, M, G1D, IND, 1);

    lstm_scan1<<<BATCH / 4, 256, scan1_smem>>>(zx1p, U1, h1p);

    gemm_ff<<<M / BM, 256, gemm_smem>>>(h1p, W2, b2, zx2p, M, G2D, H1D, 0);

    lstm_scan2<<<BATCH / 4, 256, scan2_smem>>>(zx2p, U2, h2p);

    head_kernel<<<BATCH, 32>>>(h2p, Wd, bd, out);
}

// round 16
// speedup vs baseline: 1.5180x; 1.2343x over previous
#include <cuda_runtime.h>
#include <cuda_bf16.h>
#include <math.h>
#include <float.h>
#include <stdint.h>

// Problem dims
#define T_SEQ 256
#define BATCH 512
#define IND   128
#define H1D   100
#define G1D   400     // 4*H1
#define H2D   128
#define G2D   512     // 4*H2
#define NC    19

typedef unsigned long long u64;

__device__ __forceinline__ void ffma2(u64 &d, u64 a, u64 b) {
    asm("fma.rn.f32x2 %0, %1, %2, %0;" : "+l"(d) : "l"(a), "l"(b));
}
__device__ __forceinline__ u64 pack2(float x, float y) {
    u64 r; asm("mov.b64 %0, {%1, %2};" : "=l"(r) : "f"(x), "f"(y)); return r;
}
__device__ __forceinline__ float2 unpk(u64 v) {
    float2 r; asm("mov.b64 {%0, %1}, %2;" : "=f"(r.x), "=f"(r.y) : "l"(v)); return r;
}
__device__ __forceinline__ float fsig(float a) {
    return __fdividef(1.f, 1.f + __expf(-a));
}
__device__ __forceinline__ void quad_transpose(float &a0, float &a1, float &a2,
                                               float &a3, int k) {
    float s, r;
    s = (k & 1) ? a0 : a1; r = __shfl_xor_sync(0xffffffffu, s, 1);
    if (k & 1) a0 = r; else a1 = r;
    s = (k & 1) ? a2 : a3; r = __shfl_xor_sync(0xffffffffu, s, 1);
    if (k & 1) a2 = r; else a3 = r;
    s = (k & 2) ? a0 : a2; r = __shfl_xor_sync(0xffffffffu, s, 2);
    if (k & 2) a0 = r; else a2 = r;
    s = (k & 2) ? a1 : a3; r = __shfl_xor_sync(0xffffffffu, s, 2);
    if (k & 2) a1 = r; else a3 = r;
}
__device__ __forceinline__ uint32_t smem_u32(const void* p) {
    uint32_t a; asm("{ .reg .u64 t; cvta.to.shared.u64 t, %1; cvt.u32.u64 %0, t; }"
                    : "=r"(a) : "l"(p));
    return a;
}
__device__ __forceinline__ void ldsm4(uint32_t &r0, uint32_t &r1, uint32_t &r2,
                                      uint32_t &r3, uint32_t addr) {
    asm volatile("ldmatrix.sync.aligned.m8n8.x4.shared.b16 {%0,%1,%2,%3}, [%4];"
                 : "=r"(r0), "=r"(r1), "=r"(r2), "=r"(r3) : "r"(addr));
}
__device__ __forceinline__ void mma16816(float *c, uint32_t a0, uint32_t a1,
                                         uint32_t a2, uint32_t a3,
                                         uint32_t b0, uint32_t b1) {
    asm volatile(
        "mma.sync.aligned.m16n8k16.row.col.f32.bf16.bf16.f32 "
        "{%0,%1,%2,%3}, {%4,%5,%6,%7}, {%8,%9}, {%0,%1,%2,%3};"
        : "+f"(c[0]), "+f"(c[1]), "+f"(c[2]), "+f"(c[3])
        : "r"(a0), "r"(a1), "r"(a2), "r"(a3), "r"(b0), "r"(b1));
}

// ---------------- scratch ---------------------------------------------------
__device__ float g_zx1[256u*512u*400u];   // [(t,b)][G1]
__device__ float g_h1 [256u*512u*100u];   // [(t,b)][H1]
__device__ float g_zx2[256u*512u*512u];   // [(t,b)][G2]
__device__ float g_h2 [512u*128u];        // [B][H2]
// pre-transposed weights [n][128] bf16 hi/lo (K zero-padded to 128)
__device__ __nv_bfloat16 g_w1h[400*128], g_w1l[400*128];
__device__ __nv_bfloat16 g_w2h[512*128], g_w2l[512*128];

__global__ void conv_weights(const float* __restrict__ W1, const float* __restrict__ W2)
{
    int tid = blockIdx.x * blockDim.x + threadIdx.x;
    for (int i = tid; i < 400 * 128; i += gridDim.x * blockDim.x) {
        int n = i >> 7, k = i & 127;
        float v = W1[(size_t)k * G1D + n];
        __nv_bfloat16 h = __float2bfloat16_rn(v);
        g_w1h[i] = h;
        g_w1l[i] = __float2bfloat16_rn(v - __bfloat162float(h));
    }
    for (int i = tid; i < 512 * 128; i += gridDim.x * blockDim.x) {
        int n = i >> 7, k = i & 127;
        float v = (k < H1D) ? W2[(size_t)k * G2D + n] : 0.f;
        __nv_bfloat16 h = __float2bfloat16_rn(v);
        g_w2h[i] = h;
        g_w2l[i] = __float2bfloat16_rn(v - __bfloat162float(h));
    }
}

// ---------------- mma.sync bf16 split-2 GEMM --------------------------------
// Block: 8 warps x 16 m-rows = 128-row A tile (converted once to smem hi/lo),
// n-loop over 64-wide B tiles. 3 passes (hh, hl, lh) accumulate in fp32 frags.
#define APAD 136
#define GT 256
// smem: Ah[128][APAD], Al, Bh[64][APAD], Bl (bf16)
#define GSM_AH 0
#define GSM_AL (128*APAD)
#define GSM_BH (2*128*APAD)
#define GSM_BL (2*128*APAD + 64*APAD)
#define GSM_ELEMS (2*128*APAD + 2*64*APAD)

__global__ __launch_bounds__(GT, 1)
void gemm_mma(const float* __restrict__ A,
              const __nv_bfloat16* __restrict__ Bh,
              const __nv_bfloat16* __restrict__ Bl,
              const float* __restrict__ bias, float* __restrict__ C,
              int N, int K, int mode)
{
    extern __shared__ __align__(16) __nv_bfloat16 gsm[];
    const int tid = threadIdx.x;
    const int wid = tid >> 5, lane = tid & 31;
    const int m0 = blockIdx.x * 128;

    // convert A tile (zero-pad k>=K)
    for (int idx = tid; idx < 128 * 128; idx += GT) {
        int row = idx >> 7, k = idx & 127;
        int m = m0 + row;
        float v = 0.f;
        if (k < K) {
            size_t ar;
            if (mode) { int t = m >> 9; int b = m & 511; ar = ((size_t)(b * T_SEQ + t)) * IND; }
            else      { ar = (size_t)m * K; }
            v = A[ar + k];
        }
        __nv_bfloat16 h = __float2bfloat16_rn(v);
        gsm[GSM_AH + row * APAD + k] = h;
        gsm[GSM_AL + row * APAD + k] = __float2bfloat16_rn(v - __bfloat162float(h));
    }

    // per-lane ldmatrix addresses
    const int lrow = lane & 7;
    const int aRow = wid * 16 + lrow + ((lane >> 3) & 1) * 8;
    const int aCol = ((lane >> 4) & 1) * 8;
    const int bRowL = lrow + ((lane >> 4) & 1) * 8;
    const int bCol = ((lane >> 3) & 1) * 8;
    const uint32_t sb = smem_u32(gsm);
    const uint32_t aH = sb + (uint32_t)(GSM_AH + aRow * APAD + aCol) * 2;
    const uint32_t aL = sb + (uint32_t)(GSM_AL + aRow * APAD + aCol) * 2;
    const uint32_t bH = sb + (uint32_t)(GSM_BH + bRowL * APAD + bCol) * 2;
    const uint32_t bL = sb + (uint32_t)(GSM_BL + bRowL * APAD + bCol) * 2;
    const int groupID = lane >> 2, tig = lane & 3;

    const int ntiles = (N + 63) / 64;
    for (int nt = 0; nt < ntiles; ++nt) {
        const int n0 = nt * 64;
        if (nt) __syncthreads();           // prior compute done before B overwrite
        for (int idx = tid; idx < 64 * 16; idx += GT) {
            int n = idx >> 4, k0 = (idx & 15) * 8;
            int gn = n0 + n;
            uint4 vh = make_uint4(0, 0, 0, 0), vl = vh;
            if (gn < N) {
                vh = *reinterpret_cast<const uint4*>(&Bh[(size_t)gn * 128 + k0]);
                vl = *reinterpret_cast<const uint4*>(&Bl[(size_t)gn * 128 + k0]);
            }
            *reinterpret_cast<uint4*>(&gsm[GSM_BH + n * APAD + k0]) = vh;
            *reinterpret_cast<uint4*>(&gsm[GSM_BL + n * APAD + k0]) = vl;
        }
        __syncthreads();

        float acc[8][4];
#pragma unroll
        for (int i = 0; i < 8; i++)
#pragma unroll
            for (int jj = 0; jj < 4; jj++) acc[i][jj] = 0.f;

#pragma unroll 1
        for (int pass = 0; pass < 3; ++pass) {
            uint32_t aBase = (pass == 2) ? aL : aH;
            uint32_t bBase = (pass == 1) ? bL : bH;
#pragma unroll
            for (int ks = 0; ks < 8; ++ks) {
                uint32_t a0, a1, a2, a3;
                ldsm4(a0, a1, a2, a3, aBase + (uint32_t)(ks * 16) * 2);
#pragma unroll
                for (int nf = 0; nf < 4; ++nf) {
                    uint32_t b0, b1, b2, b3;
                    ldsm4(b0, b1, b2, b3,
                          bBase + (uint32_t)(nf * 16 * APAD + ks * 16) * 2);
                    mma16816(acc[nf * 2 + 0], a0, a1, a2, a3, b0, b1);
                    mma16816(acc[nf * 2 + 1], a0, a1, a2, a3, b2, b3);
                }
            }
        }

        // epilogue: bias + store
        const int mA = m0 + wid * 16 + groupID;
#pragma unroll
        for (int nf = 0; nf < 8; ++nf) {
            int col = n0 + nf * 8 + tig * 2;
            if (col < N) {
                float b0v = bias[col], b1v = bias[col + 1];
                float2 v0 = make_float2(acc[nf][0] + b0v, acc[nf][1] + b1v);
                float2 v1 = make_float2(acc[nf][2] + b0v, acc[nf][3] + b1v);
                *reinterpret_cast<float2*>(&C[(size_t)mA * N + col]) = v0;
                *reinterpret_cast<float2*>(&C[(size_t)(mA + 8) * N + col]) = v1;
            }
        }
    }
}

// ---------------- layer-1 scan (R13) ----------------------------------------
#define U1REGJ 80
#define U1SMJ  20
#define H1P    104
__global__ __launch_bounds__(256, 1)
void lstm_scan1(const float* __restrict__ zx, const float* __restrict__ U,
                float* __restrict__ hout)
{
    extern __shared__ __align__(16) float sm1[];
    float* U1sT = sm1;
    float* hT   = sm1 + 512 * U1SMJ;

    const int tid = threadIdx.x;
    const int j4 = tid >> 2;
    const int k  = tid & 3;
    const int jA = (j4 < 50) ? j4 : 49;
    const int jB = jA + 50;
    const int colA = k * H1D + jA;
    const int colB = k * H1D + jB;
    const int b0 = blockIdx.x * 4;

    u64 UpA[U1REGJ / 2], UpB[U1REGJ / 2];
#pragma unroll
    for (int p = 0; p < U1REGJ / 2; ++p) {
        UpA[p] = pack2(U[(2 * p) * G1D + colA], U[(2 * p + 1) * G1D + colA]);
        UpB[p] = pack2(U[(2 * p) * G1D + colB], U[(2 * p + 1) * G1D + colB]);
    }
#pragma unroll
    for (int jj = 0; jj < U1SMJ; ++jj) {
        U1sT[tid * U1SMJ + jj]         = U[(U1REGJ + jj) * G1D + colA];
        U1sT[(256 + tid) * U1SMJ + jj] = U[(U1REGJ + jj) * G1D + colB];
    }
    for (int i = tid; i < 2 * 4 * H1P; i += 256) hT[i] = 0.f;

    float cA = 0.f, cB = 0.f;
    const float* zbA = zx + colA;
    const float* zbB = zx + colB;
    float zA0 = zbA[((size_t)0 * BATCH + b0 + 0) * G1D];
    float zA1 = zbA[((size_t)0 * BATCH + b0 + 1) * G1D];
    float zA2 = zbA[((size_t)0 * BATCH + b0 + 2) * G1D];
    float zA3 = zbA[((size_t)0 * BATCH + b0 + 3) * G1D];
    float zB0 = zbB[((size_t)0 * BATCH + b0 + 0) * G1D];
    float zB1 = zbB[((size_t)0 * BATCH + b0 + 1) * G1D];
    float zB2 = zbB[((size_t)0 * BATCH + b0 + 2) * G1D];
    float zB3 = zbB[((size_t)0 * BATCH + b0 + 3) * G1D];
    __syncthreads();

#pragma unroll 1
    for (int t = 0; t < T_SEQ; ++t) {
        int tn = (t + 1 < T_SEQ) ? (t + 1) : t;
        float nA0 = zbA[((size_t)tn * BATCH + b0 + 0) * G1D];
        float nA1 = zbA[((size_t)tn * BATCH + b0 + 1) * G1D];
        float nA2 = zbA[((size_t)tn * BATCH + b0 + 2) * G1D];
        float nA3 = zbA[((size_t)tn * BATCH + b0 + 3) * G1D];
        float nB0 = zbB[((size_t)tn * BATCH + b0 + 0) * G1D];
        float nB1 = zbB[((size_t)tn * BATCH + b0 + 1) * G1D];
        float nB2 = zbB[((size_t)tn * BATCH + b0 + 2) * G1D];
        float nB3 = zbB[((size_t)tn * BATCH + b0 + 3) * G1D];

        const float* hp = hT + (t & 1) * (4 * H1P);
        u64 aA0 = 0ull, aA1 = 0ull, aA2 = 0ull, aA3 = 0ull;
        u64 aB0 = 0ull, aB1 = 0ull, aB2 = 0ull, aB3 = 0ull;
#pragma unroll
        for (int p4 = 0; p4 < U1REGJ / 4; ++p4) {
            int j0 = 4 * p4;
            ulonglong2 h0 = *reinterpret_cast<const ulonglong2*>(&hp[0 * H1P + j0]);
            ulonglong2 h1 = *reinterpret_cast<const ulonglong2*>(&hp[1 * H1P + j0]);
            ulonglong2 h2 = *reinterpret_cast<const ulonglong2*>(&hp[2 * H1P + j0]);
            ulonglong2 h3 = *reinterpret_cast<const ulonglong2*>(&hp[3 * H1P + j0]);
            u64 ua = UpA[2 * p4], ub = UpA[2 * p4 + 1];
            u64 va = UpB[2 * p4], vb = UpB[2 * p4 + 1];
            ffma2(aA0, h0.x, ua); ffma2(aA0, h0.y, ub);
            ffma2(aA1, h1.x, ua); ffma2(aA1, h1.y, ub);
            ffma2(aA2, h2.x, ua); ffma2(aA2, h2.y, ub);
            ffma2(aA3, h3.x, ua); ffma2(aA3, h3.y, ub);
            ffma2(aB0, h0.x, va); ffma2(aB0, h0.y, vb);
            ffma2(aB1, h1.x, va); ffma2(aB1, h1.y, vb);
            ffma2(aB2, h2.x, va); ffma2(aB2, h2.y, vb);
            ffma2(aB3, h3.x, va); ffma2(aB3, h3.y, vb);
        }
#pragma unroll
        for (int q = 0; q < U1SMJ / 4; ++q) {
            int j0 = U1REGJ + 4 * q;
            ulonglong2 uA = *reinterpret_cast<const ulonglong2*>(&U1sT[tid * U1SMJ + 4 * q]);
            ulonglong2 uB = *reinterpret_cast<const ulonglong2*>(&U1sT[(256 + tid) * U1SMJ + 4 * q]);
            ulonglong2 h0 = *reinterpret_cast<const ulonglong2*>(&hp[0 * H1P + j0]);
            ulonglong2 h1 = *reinterpret_cast<const ulonglong2*>(&hp[1 * H1P + j0]);
            ulonglong2 h2 = *reinterpret_cast<const ulonglong2*>(&hp[2 * H1P + j0]);
            ulonglong2 h3 = *reinterpret_cast<const ulonglong2*>(&hp[3 * H1P + j0]);
            ffma2(aA0, h0.x, uA.x); ffma2(aA0, h0.y, uA.y);
            ffma2(aA1, h1.x, uA.x); ffma2(aA1, h1.y, uA.y);
            ffma2(aA2, h2.x, uA.x); ffma2(aA2, h2.y, uA.y);
            ffma2(aA3, h3.x, uA.x); ffma2(aA3, h3.y, uA.y);
            ffma2(aB0, h0.x, uB.x); ffma2(aB0, h0.y, uB.y);
            ffma2(aB1, h1.x, uB.x); ffma2(aB1, h1.y, uB.y);
            ffma2(aB2, h2.x, uB.x); ffma2(aB2, h2.y, uB.y);
            ffma2(aB3, h3.x, uB.x); ffma2(aB3, h3.y, uB.y);
        }
        float2 sA0 = unpk(aA0), sA1 = unpk(aA1), sA2 = unpk(aA2), sA3 = unpk(aA3);
        float2 sB0 = unpk(aB0), sB1 = unpk(aB1), sB2 = unpk(aB2), sB3 = unpk(aB3);
        float vA0 = sA0.x + sA0.y + zA0;
        float vA1 = sA1.x + sA1.y + zA1;
        float vA2 = sA2.x + sA2.y + zA2;
        float vA3 = sA3.x + sA3.y + zA3;
        float vB0 = sB0.x + sB0.y + zB0;
        float vB1 = sB1.x + sB1.y + zB1;
        float vB2 = sB2.x + sB2.y + zB2;
        float vB3 = sB3.x + sB3.y + zB3;
        if (k == 2) {
            vA0 = fmaxf(vA0, 0.f); vA1 = fmaxf(vA1, 0.f);
            vA2 = fmaxf(vA2, 0.f); vA3 = fmaxf(vA3, 0.f);
            vB0 = fmaxf(vB0, 0.f); vB1 = fmaxf(vB1, 0.f);
            vB2 = fmaxf(vB2, 0.f); vB3 = fmaxf(vB3, 0.f);
        } else {
            vA0 = fsig(vA0); vA1 = fsig(vA1); vA2 = fsig(vA2); vA3 = fsig(vA3);
            vB0 = fsig(vB0); vB1 = fsig(vB1); vB2 = fsig(vB2); vB3 = fsig(vB3);
        }
        quad_transpose(vA0, vA1, vA2, vA3, k);
        quad_transpose(vB0, vB1, vB2, vB3, k);
        {
            cA = fmaf(vA1, cA, vA0 * vA2);
            float h = vA3 * fmaxf(cA, 0.f);
            hT[(1 - (t & 1)) * (4 * H1P) + k * H1P + jA] = h;
            if (j4 < 50) hout[((size_t)t * BATCH + b0 + k) * H1D + jA] = h;
        }
        {
            cB = fmaf(vB1, cB, vB0 * vB2);
            float h = vB3 * fmaxf(cB, 0.f);
            hT[(1 - (t & 1)) * (4 * H1P) + k * H1P + jB] = h;
            if (j4 < 50) hout[((size_t)t * BATCH + b0 + k) * H1D + jB] = h;
        }
        zA0 = nA0; zA1 = nA1; zA2 = nA2; zA3 = nA3;
        zB0 = nB0; zB1 = nB1; zB2 = nB2; zB3 = nB3;
        __syncthreads();
    }
}

// ---------------- layer-2 scan (R13) ----------------------------------------
#define U2REGJ 80
#define U2SMJ  48
#define U2P    52
__global__ __launch_bounds__(256, 1)
void lstm_scan2(const float* __restrict__ zx, const float* __restrict__ U,
                float* __restrict__ h2out)
{
    extern __shared__ __align__(16) float sm2[];
    float* U2sT = sm2;
    float* hT   = sm2 + 512 * U2P;

    const int tid = threadIdx.x;
    const int j  = tid >> 2;
    const int k  = tid & 3;
    const int jA = j, jB = j + 64;
    const int colA = k * H2D + jA;
    const int colB = k * H2D + jB;
    const int b0 = blockIdx.x * 4;

    u64 UpA[U2REGJ / 2], UpB[U2REGJ / 2];
#pragma unroll
    for (int p = 0; p < U2REGJ / 2; ++p) {
        UpA[p] = pack2(U[(2 * p) * G2D + colA], U[(2 * p + 1) * G2D + colA]);
        UpB[p] = pack2(U[(2 * p) * G2D + colB], U[(2 * p + 1) * G2D + colB]);
    }
    for (int idx = tid; idx < U2SMJ * G2D; idx += 256) {
        int r = idx >> 9;
        int cc = idx & 511;
        int jj = cc & 127, kk = cc >> 7;
        int slot = (jj < 64) ? (4 * jj + kk) : (256 + 4 * (jj - 64) + kk);
        U2sT[slot * U2P + r] = U[(size_t)(U2REGJ + r) * G2D + cc];
    }
    for (int i = tid; i < 2 * 4 * H2D; i += 256) hT[i] = 0.f;

    float cA = 0.f, cB = 0.f;
    const float* zbA = zx + colA;
    const float* zbB = zx + colB;
    float zA0 = zbA[((size_t)0 * BATCH + b0 + 0) * G2D];
    float zA1 = zbA[((size_t)0 * BATCH + b0 + 1) * G2D];
    float zA2 = zbA[((size_t)0 * BATCH + b0 + 2) * G2D];
    float zA3 = zbA[((size_t)0 * BATCH + b0 + 3) * G2D];
    float zB0 = zbB[((size_t)0 * BATCH + b0 + 0) * G2D];
    float zB1 = zbB[((size_t)0 * BATCH + b0 + 1) * G2D];
    float zB2 = zbB[((size_t)0 * BATCH + b0 + 2) * G2D];
    float zB3 = zbB[((size_t)0 * BATCH + b0 + 3) * G2D];
    __syncthreads();

#pragma unroll 1
    for (int t = 0; t < T_SEQ; ++t) {
        int tn = (t + 1 < T_SEQ) ? (t + 1) : t;
        float nA0 = zbA[((size_t)tn * BATCH + b0 + 0) * G2D];
        float nA1 = zbA[((size_t)tn * BATCH + b0 + 1) * G2D];
        float nA2 = zbA[((size_t)tn * BATCH + b0 + 2) * G2D];
        float nA3 = zbA[((size_t)tn * BATCH + b0 + 3) * G2D];
        float nB0 = zbB[((size_t)tn * BATCH + b0 + 0) * G2D];
        float nB1 = zbB[((size_t)tn * BATCH + b0 + 1) * G2D];
        float nB2 = zbB[((size_t)tn * BATCH + b0 + 2) * G2D];
        float nB3 = zbB[((size_t)tn * BATCH + b0 + 3) * G2D];

        const float* hp = hT + (t & 1) * (4 * H2D);
        u64 aA0 = 0ull, aA1 = 0ull, aA2 = 0ull, aA3 = 0ull;
        u64 aB0 = 0ull, aB1 = 0ull, aB2 = 0ull, aB3 = 0ull;
#pragma unroll
        for (int p4 = 0; p4 < U2REGJ / 4; ++p4) {
            int j0 = 4 * p4;
            ulonglong2 h0 = *reinterpret_cast<const ulonglong2*>(&hp[0 * H2D + j0]);
            ulonglong2 h1 = *reinterpret_cast<const ulonglong2*>(&hp[1 * H2D + j0]);
            ulonglong2 h2 = *reinterpret_cast<const ulonglong2*>(&hp[2 * H2D + j0]);
            ulonglong2 h3 = *reinterpret_cast<const ulonglong2*>(&hp[3 * H2D + j0]);
            u64 ua = UpA[2 * p4], ub = UpA[2 * p4 + 1];
            u64 va = UpB[2 * p4], vb = UpB[2 * p4 + 1];
            ffma2(aA0, h0.x, ua); ffma2(aA0, h0.y, ub);
            ffma2(aA1, h1.x, ua); ffma2(aA1, h1.y, ub);
            ffma2(aA2, h2.x, ua); ffma2(aA2, h2.y, ub);
            ffma2(aA3, h3.x, ua); ffma2(aA3, h3.y, ub);
            ffma2(aB0, h0.x, va); ffma2(aB0, h0.y, vb);
            ffma2(aB1, h1.x, va); ffma2(aB1, h1.y, vb);
            ffma2(aB2, h2.x, va); ffma2(aB2, h2.y, vb);
            ffma2(aB3, h3.x, va); ffma2(aB3, h3.y, vb);
        }
#pragma unroll
        for (int q = 0; q < U2SMJ / 4; ++q) {
            int j0 = U2REGJ + 4 * q;
            ulonglong2 uA = *reinterpret_cast<const ulonglong2*>(&U2sT[tid * U2P + 4 * q]);
            ulonglong2 uB = *reinterpret_cast<const ulonglong2*>(&U2sT[(256 + tid) * U2P + 4 * q]);
            ulonglong2 h0 = *reinterpret_cast<const ulonglong2*>(&hp[0 * H2D + j0]);
            ulonglong2 h1 = *reinterpret_cast<const ulonglong2*>(&hp[1 * H2D + j0]);
            ulonglong2 h2 = *reinterpret_cast<const ulonglong2*>(&hp[2 * H2D + j0]);
            ulonglong2 h3 = *reinterpret_cast<const ulonglong2*>(&hp[3 * H2D + j0]);
            ffma2(aA0, h0.x, uA.x); ffma2(aA0, h0.y, uA.y);
            ffma2(aA1, h1.x, uA.x); ffma2(aA1, h1.y, uA.y);
            ffma2(aA2, h2.x, uA.x); ffma2(aA2, h2.y, uA.y);
            ffma2(aA3, h3.x, uA.x); ffma2(aA3, h3.y, uA.y);
            ffma2(aB0, h0.x, uB.x); ffma2(aB0, h0.y, uB.y);
            ffma2(aB1, h1.x, uB.x); ffma2(aB1, h1.y, uB.y);
            ffma2(aB2, h2.x, uB.x); ffma2(aB2, h2.y, uB.y);
            ffma2(aB3, h3.x, uB.x); ffma2(aB3, h3.y, uB.y);
        }
        float2 sA0 = unpk(aA0), sA1 = unpk(aA1), sA2 = unpk(aA2), sA3 = unpk(aA3);
        float2 sB0 = unpk(aB0), sB1 = unpk(aB1), sB2 = unpk(aB2), sB3 = unpk(aB3);
        float vA0 = sA0.x + sA0.y + zA0;
        float vA1 = sA1.x + sA1.y + zA1;
        float vA2 = sA2.x + sA2.y + zA2;
        float vA3 = sA3.x + sA3.y + zA3;
        float vB0 = sB0.x + sB0.y + zB0;
        float vB1 = sB1.x + sB1.y + zB1;
        float vB2 = sB2.x + sB2.y + zB2;
        float vB3 = sB3.x + sB3.y + zB3;
        if (k == 2) {
            vA0 = fmaxf(vA0, 0.f); vA1 = fmaxf(vA1, 0.f);
            vA2 = fmaxf(vA2, 0.f); vA3 = fmaxf(vA3, 0.f);
            vB0 = fmaxf(vB0, 0.f); vB1 = fmaxf(vB1, 0.f);
            vB2 = fmaxf(vB2, 0.f); vB3 = fmaxf(vB3, 0.f);
        } else {
            vA0 = fsig(vA0); vA1 = fsig(vA1); vA2 = fsig(vA2); vA3 = fsig(vA3);
            vB0 = fsig(vB0); vB1 = fsig(vB1); vB2 = fsig(vB2); vB3 = fsig(vB3);
        }
        quad_transpose(vA0, vA1, vA2, vA3, k);
        quad_transpose(vB0, vB1, vB2, vB3, k);
        {
            cA = fmaf(vA1, cA, vA0 * vA2);
            float h = vA3 * fmaxf(cA, 0.f);
            hT[(1 - (t & 1)) * (4 * H2D) + k * H2D + jA] = h;
            if (t == T_SEQ - 1) h2out[(b0 + k) * H2D + jA] = h;
        }
        {
            cB = fmaf(vB1, cB, vB0 * vB2);
            float h = vB3 * fmaxf(cB, 0.f);
            hT[(1 - (t & 1)) * (4 * H2D) + k * H2D + jB] = h;
            if (t == T_SEQ - 1) h2out[(b0 + k) * H2D + jB] = h;
        }
        zA0 = nA0; zA1 = nA1; zA2 = nA2; zA3 = nA3;
        zB0 = nB0; zB1 = nB1; zB2 = nB2; zB3 = nB3;
        __syncthreads();
    }
}

// ---------------- dense head + softmax -------------------------------------
__global__ void head_kernel(const float* __restrict__ h2, const float* __restrict__ Wd,
                            const float* __restrict__ bd, float* __restrict__ out)
{
    __shared__ float hsh[H2D];
    const int b = blockIdx.x;
    const int lane = threadIdx.x;
    for (int j = lane; j < H2D; j += 32) hsh[j] = h2[b * H2D + j];
    __syncthreads();

    float acc = 0.f;
    if (lane < NC) {
        acc = bd[lane];
#pragma unroll
        for (int j = 0; j < H2D; ++j) acc = fmaf(hsh[j], Wd[j * NC + lane], acc);
    }
    float v = (lane < NC) ? acc : -FLT_MAX;
#pragma unroll
    for (int off = 16; off > 0; off >>= 1)
        v = fmaxf(v, __shfl_xor_sync(0xffffffffu, v, off));
    float e = (lane < NC) ? expf(acc - v) : 0.f;
    float s = e;
#pragma unroll
    for (int off = 16; off > 0; off >>= 1)
        s += __shfl_xor_sync(0xffffffffu, s, off);
    if (lane < NC) out[b * NC + lane] = e / s;
}

// ---------------- launch ----------------------------------------------------
extern "C" void kernel_launch(void* const* d_in, const int* in_sizes, int n_in,
                              void* d_out, int out_size)
{
    const float* x  = (const float*)d_in[0];
    const float* W1 = (const float*)d_in[1];
    const float* U1 = (const float*)d_in[2];
    const float* b1 = (const float*)d_in[3];
    const float* W2 = (const float*)d_in[4];
    const float* U2 = (const float*)d_in[5];
    const float* b2 = (const float*)d_in[6];
    const float* Wd = (const float*)d_in[7];
    const float* bd = (const float*)d_in[8];
    float* out = (float*)d_out;

    const int gemm_smem  = GSM_ELEMS * 2;                         // 104448
    const int scan1_smem = (512 * U1SMJ + 2 * 4 * H1P) * 4;
    const int scan2_smem = (512 * U2P + 2 * 4 * H2D) * 4;
    cudaFuncSetAttribute(gemm_mma,   cudaFuncAttributeMaxDynamicSharedMemorySize, gemm_smem);
    cudaFuncSetAttribute(lstm_scan1, cudaFuncAttributeMaxDynamicSharedMemorySize, scan1_smem);
    cudaFuncSetAttribute(lstm_scan2, cudaFuncAttributeMaxDynamicSharedMemorySize, scan2_smem);

    float *zx1p, *h1p, *zx2p, *h2p;
    cudaGetSymbolAddress((void**)&zx1p, g_zx1);
    cudaGetSymbolAddress((void**)&h1p,  g_h1);
    cudaGetSymbolAddress((void**)&zx2p, g_zx2);
    cudaGetSymbolAddress((void**)&h2p,  g_h2);
    __nv_bfloat16 *w1h, *w1l, *w2h, *w2l;
    cudaGetSymbolAddress((void**)&w1h, g_w1h);
    cudaGetSymbolAddress((void**)&w1l, g_w1l);
    cudaGetSymbolAddress((void**)&w2h, g_w2h);
    cudaGetSymbolAddress((void**)&w2l, g_w2l);

    const int M = T_SEQ * BATCH;

    conv_weights<<<64, 256>>>(W1, W2);

    gemm_mma<<<M / 128, GT, gemm_smem>>>(x, w1h, w1l, b1, zx1p, G1D, IND, 1);

    lstm_scan1<<<BATCH / 4, 256, scan1_smem>>>(zx1p, U1, h1p);

    gemm_mma<<<M / 128, GT, gemm_smem>>>(h1p, w2h, w2l, b2, zx2p, G2D, H1D, 0);

    lstm_scan2<<<BATCH / 4, 256, scan2_smem>>>(zx2p, U2, h2p);

    head_kernel<<<BATCH, 32>>>(h2p, Wd, bd, out);
}

// round 17
// speedup vs baseline: 1.5432x; 1.0166x over previous
#include <cuda_runtime.h>
#include <cuda_bf16.h>
#include <math.h>
#include <float.h>
#include <stdint.h>

// Problem dims
#define T_SEQ 256
#define BATCH 512
#define IND   128
#define H1D   100
#define G1D   400     // 4*H1
#define H2D   128
#define G2D   512     // 4*H2
#define NC    19

typedef unsigned long long u64;

__device__ __forceinline__ void ffma2(u64 &d, u64 a, u64 b) {
    asm("fma.rn.f32x2 %0, %1, %2, %0;" : "+l"(d) : "l"(a), "l"(b));
}
__device__ __forceinline__ u64 pack2(float x, float y) {
    u64 r; asm("mov.b64 %0, {%1, %2};" : "=l"(r) : "f"(x), "f"(y)); return r;
}
__device__ __forceinline__ float2 unpk(u64 v) {
    float2 r; asm("mov.b64 {%0, %1}, %2;" : "=f"(r.x), "=f"(r.y) : "l"(v)); return r;
}
__device__ __forceinline__ float fsig(float a) {
    return __fdividef(1.f, 1.f + __expf(-a));
}
__device__ __forceinline__ void quad_transpose(float &a0, float &a1, float &a2,
                                               float &a3, int k) {
    float s, r;
    s = (k & 1) ? a0 : a1; r = __shfl_xor_sync(0xffffffffu, s, 1);
    if (k & 1) a0 = r; else a1 = r;
    s = (k & 1) ? a2 : a3; r = __shfl_xor_sync(0xffffffffu, s, 1);
    if (k & 1) a2 = r; else a3 = r;
    s = (k & 2) ? a0 : a2; r = __shfl_xor_sync(0xffffffffu, s, 2);
    if (k & 2) a0 = r; else a2 = r;
    s = (k & 2) ? a1 : a3; r = __shfl_xor_sync(0xffffffffu, s, 2);
    if (k & 2) a1 = r; else a3 = r;
}
__device__ __forceinline__ uint32_t smem_u32(const void* p) {
    uint32_t a; asm("{ .reg .u64 t; cvta.to.shared.u64 t, %1; cvt.u32.u64 %0, t; }"
                    : "=r"(a) : "l"(p));
    return a;
}
__device__ __forceinline__ void ldsm4(uint32_t &r0, uint32_t &r1, uint32_t &r2,
                                      uint32_t &r3, uint32_t addr) {
    asm volatile("ldmatrix.sync.aligned.m8n8.x4.shared.b16 {%0,%1,%2,%3}, [%4];"
                 : "=r"(r0), "=r"(r1), "=r"(r2), "=r"(r3) : "r"(addr));
}
__device__ __forceinline__ void mma16816(float *c, uint32_t a0, uint32_t a1,
                                         uint32_t a2, uint32_t a3,
                                         uint32_t b0, uint32_t b1) {
    asm volatile(
        "mma.sync.aligned.m16n8k16.row.col.f32.bf16.bf16.f32 "
        "{%0,%1,%2,%3}, {%4,%5,%6,%7}, {%8,%9}, {%0,%1,%2,%3};"
        : "+f"(c[0]), "+f"(c[1]), "+f"(c[2]), "+f"(c[3])
        : "r"(a0), "r"(a1), "r"(a2), "r"(a3), "r"(b0), "r"(b1));
}

// ---------------- scratch ---------------------------------------------------
__device__ float g_zx1[256u*512u*400u];   // [(t,b)][G1]
__device__ float g_h1 [256u*512u*100u];   // [(t,b)][H1]
__device__ float g_zx2[256u*512u*512u];   // [(t,b)][G2]
__device__ float g_h2 [512u*128u];        // [B][H2]
__device__ __nv_bfloat16 g_w1h[400*128], g_w1l[400*128];
__device__ __nv_bfloat16 g_w2h[512*128], g_w2l[512*128];

__global__ void conv_weights(const float* __restrict__ W1, const float* __restrict__ W2)
{
    int tid = blockIdx.x * blockDim.x + threadIdx.x;
    for (int i = tid; i < 400 * 128; i += gridDim.x * blockDim.x) {
        int n = i >> 7, k = i & 127;
        float v = W1[(size_t)k * G1D + n];
        __nv_bfloat16 h = __float2bfloat16_rn(v);
        g_w1h[i] = h;
        g_w1l[i] = __float2bfloat16_rn(v - __bfloat162float(h));
    }
    for (int i = tid; i < 512 * 128; i += gridDim.x * blockDim.x) {
        int n = i >> 7, k = i & 127;
        float v = (k < H1D) ? W2[(size_t)k * G2D + n] : 0.f;
        __nv_bfloat16 h = __float2bfloat16_rn(v);
        g_w2h[i] = h;
        g_w2l[i] = __float2bfloat16_rn(v - __bfloat162float(h));
    }
}

// ---------------- mma.sync bf16 split-2 GEMM, BM=64, occ 2 -------------------
// Warp w: m-rows (w&3)*16, n-half (w>>2)*32. Fused passes: per k-step load
// A-hi/A-lo and per nf B-hi/B-lo once, issue hh+hl+lh mmas (6 ldsm4 / 24 mma
// per ks). smem 69.6KB -> 2 blocks/SM.
#define APAD 136
#define GT 256
#define GSM_AH 0
#define GSM_AL (64*APAD)
#define GSM_BH (2*64*APAD)
#define GSM_BL (3*64*APAD)
#define GSM_ELEMS (4*64*APAD)

__global__ __launch_bounds__(GT, 2)
void gemm_mma(const float* __restrict__ A,
              const __nv_bfloat16* __restrict__ Bh,
              const __nv_bfloat16* __restrict__ Bl,
              const float* __restrict__ bias, float* __restrict__ C,
              int N, int K, int mode)
{
    extern __shared__ __align__(16) __nv_bfloat16 gsm[];
    const int tid = threadIdx.x;
    const int wid = tid >> 5, lane = tid & 31;
    const int m0 = blockIdx.x * 64;

    // convert A tile (64 rows x 128 k, zero-pad k>=K)
    for (int idx = tid; idx < 64 * 128; idx += GT) {
        int row = idx >> 7, k = idx & 127;
        int m = m0 + row;
        float v = 0.f;
        if (k < K) {
            size_t ar;
            if (mode) { int t = m >> 9; int b = m & 511; ar = ((size_t)(b * T_SEQ + t)) * IND; }
            else      { ar = (size_t)m * K; }
            v = A[ar + k];
        }
        __nv_bfloat16 h = __float2bfloat16_rn(v);
        gsm[GSM_AH + row * APAD + k] = h;
        gsm[GSM_AL + row * APAD + k] = __float2bfloat16_rn(v - __bfloat162float(h));
    }

    const int lrow = lane & 7;
    const int mwarp = (wid & 3) * 16;
    const int nhalf = wid >> 2;
    const int aRow = mwarp + lrow + ((lane >> 3) & 1) * 8;
    const int aCol = ((lane >> 4) & 1) * 8;
    const int bRowL = lrow + ((lane >> 4) & 1) * 8;
    const int bCol = ((lane >> 3) & 1) * 8;
    const uint32_t sb = smem_u32(gsm);
    const uint32_t aH = sb + (uint32_t)(GSM_AH + aRow * APAD + aCol) * 2;
    const uint32_t aL = sb + (uint32_t)(GSM_AL + aRow * APAD + aCol) * 2;
    const uint32_t bHb = sb + (uint32_t)(GSM_BH + bRowL * APAD + bCol) * 2;
    const uint32_t bLb = sb + (uint32_t)(GSM_BL + bRowL * APAD + bCol) * 2;
    const int groupID = lane >> 2, tig = lane & 3;

    const int ntiles = (N + 63) / 64;
    for (int nt = 0; nt < ntiles; ++nt) {
        const int n0 = nt * 64;
        if (nt) __syncthreads();
        for (int idx = tid; idx < 64 * 16; idx += GT) {
            int n = idx >> 4, k0 = (idx & 15) * 8;
            int gn = n0 + n;
            uint4 vh = make_uint4(0, 0, 0, 0), vl = vh;
            if (gn < N) {
                vh = *reinterpret_cast<const uint4*>(&Bh[(size_t)gn * 128 + k0]);
                vl = *reinterpret_cast<const uint4*>(&Bl[(size_t)gn * 128 + k0]);
            }
            *reinterpret_cast<uint4*>(&gsm[GSM_BH + n * APAD + k0]) = vh;
            *reinterpret_cast<uint4*>(&gsm[GSM_BL + n * APAD + k0]) = vl;
        }
        __syncthreads();

        float acc[4][4];
#pragma unroll
        for (int i = 0; i < 4; i++)
#pragma unroll
            for (int jj = 0; jj < 4; jj++) acc[i][jj] = 0.f;

#pragma unroll
        for (int ks = 0; ks < 8; ++ks) {
            uint32_t ah0, ah1, ah2, ah3, al0, al1, al2, al3;
            ldsm4(ah0, ah1, ah2, ah3, aH + (uint32_t)(ks * 16) * 2);
            ldsm4(al0, al1, al2, al3, aL + (uint32_t)(ks * 16) * 2);
#pragma unroll
            for (int nf = 0; nf < 2; ++nf) {
                int nfg = nhalf * 2 + nf;
                uint32_t off = (uint32_t)(nfg * 16 * APAD + ks * 16) * 2;
                uint32_t bh0, bh1, bh2, bh3, bl0, bl1, bl2, bl3;
                ldsm4(bh0, bh1, bh2, bh3, bHb + off);
                ldsm4(bl0, bl1, bl2, bl3, bLb + off);
                float* c0 = acc[nf * 2 + 0];
                float* c1 = acc[nf * 2 + 1];
                mma16816(c0, ah0, ah1, ah2, ah3, bh0, bh1);   // hh
                mma16816(c1, ah0, ah1, ah2, ah3, bh2, bh3);
                mma16816(c0, ah0, ah1, ah2, ah3, bl0, bl1);   // hl
                mma16816(c1, ah0, ah1, ah2, ah3, bl2, bl3);
                mma16816(c0, al0, al1, al2, al3, bh0, bh1);   // lh
                mma16816(c1, al0, al1, al2, al3, bh2, bh3);
            }
        }

        const int mA = m0 + mwarp + groupID;
#pragma unroll
        for (int f = 0; f < 4; ++f) {
            int col = n0 + nhalf * 32 + f * 8 + tig * 2;
            if (col < N) {
                float b0v = bias[col], b1v = bias[col + 1];
                float2 v0 = make_float2(acc[f][0] + b0v, acc[f][1] + b1v);
                float2 v1 = make_float2(acc[f][2] + b0v, acc[f][3] + b1v);
                *reinterpret_cast<float2*>(&C[(size_t)mA * N + col]) = v0;
                *reinterpret_cast<float2*>(&C[(size_t)(mA + 8) * N + col]) = v1;
            }
        }
    }
}

// ---------------- layer-1 scan (R13) ----------------------------------------
#define U1REGJ 80
#define U1SMJ  20
#define H1P    104
__global__ __launch_bounds__(256, 1)
void lstm_scan1(const float* __restrict__ zx, const float* __restrict__ U,
                float* __restrict__ hout)
{
    extern __shared__ __align__(16) float sm1[];
    float* U1sT = sm1;
    float* hT   = sm1 + 512 * U1SMJ;

    const int tid = threadIdx.x;
    const int j4 = tid >> 2;
    const int k  = tid & 3;
    const int jA = (j4 < 50) ? j4 : 49;
    const int jB = jA + 50;
    const int colA = k * H1D + jA;
    const int colB = k * H1D + jB;
    const int b0 = blockIdx.x * 4;

    u64 UpA[U1REGJ / 2], UpB[U1REGJ / 2];
#pragma unroll
    for (int p = 0; p < U1REGJ / 2; ++p) {
        UpA[p] = pack2(U[(2 * p) * G1D + colA], U[(2 * p + 1) * G1D + colA]);
        UpB[p] = pack2(U[(2 * p) * G1D + colB], U[(2 * p + 1) * G1D + colB]);
    }
#pragma unroll
    for (int jj = 0; jj < U1SMJ; ++jj) {
        U1sT[tid * U1SMJ + jj]         = U[(U1REGJ + jj) * G1D + colA];
        U1sT[(256 + tid) * U1SMJ + jj] = U[(U1REGJ + jj) * G1D + colB];
    }
    for (int i = tid; i < 2 * 4 * H1P; i += 256) hT[i] = 0.f;

    float cA = 0.f, cB = 0.f;
    const float* zbA = zx + colA;
    const float* zbB = zx + colB;
    float zA0 = zbA[((size_t)0 * BATCH + b0 + 0) * G1D];
    float zA1 = zbA[((size_t)0 * BATCH + b0 + 1) * G1D];
    float zA2 = zbA[((size_t)0 * BATCH + b0 + 2) * G1D];
    float zA3 = zbA[((size_t)0 * BATCH + b0 + 3) * G1D];
    float zB0 = zbB[((size_t)0 * BATCH + b0 + 0) * G1D];
    float zB1 = zbB[((size_t)0 * BATCH + b0 + 1) * G1D];
    float zB2 = zbB[((size_t)0 * BATCH + b0 + 2) * G1D];
    float zB3 = zbB[((size_t)0 * BATCH + b0 + 3) * G1D];
    __syncthreads();

#pragma unroll 1
    for (int t = 0; t < T_SEQ; ++t) {
        int tn = (t + 1 < T_SEQ) ? (t + 1) : t;
        float nA0 = zbA[((size_t)tn * BATCH + b0 + 0) * G1D];
        float nA1 = zbA[((size_t)tn * BATCH + b0 + 1) * G1D];
        float nA2 = zbA[((size_t)tn * BATCH + b0 + 2) * G1D];
        float nA3 = zbA[((size_t)tn * BATCH + b0 + 3) * G1D];
        float nB0 = zbB[((size_t)tn * BATCH + b0 + 0) * G1D];
        float nB1 = zbB[((size_t)tn * BATCH + b0 + 1) * G1D];
        float nB2 = zbB[((size_t)tn * BATCH + b0 + 2) * G1D];
        float nB3 = zbB[((size_t)tn * BATCH + b0 + 3) * G1D];

        const float* hp = hT + (t & 1) * (4 * H1P);
        u64 aA0 = 0ull, aA1 = 0ull, aA2 = 0ull, aA3 = 0ull;
        u64 aB0 = 0ull, aB1 = 0ull, aB2 = 0ull, aB3 = 0ull;
#pragma unroll
        for (int p4 = 0; p4 < U1REGJ / 4; ++p4) {
            int j0 = 4 * p4;
            ulonglong2 h0 = *reinterpret_cast<const ulonglong2*>(&hp[0 * H1P + j0]);
            ulonglong2 h1 = *reinterpret_cast<const ulonglong2*>(&hp[1 * H1P + j0]);
            ulonglong2 h2 = *reinterpret_cast<const ulonglong2*>(&hp[2 * H1P + j0]);
            ulonglong2 h3 = *reinterpret_cast<const ulonglong2*>(&hp[3 * H1P + j0]);
            u64 ua = UpA[2 * p4], ub = UpA[2 * p4 + 1];
            u64 va = UpB[2 * p4], vb = UpB[2 * p4 + 1];
            ffma2(aA0, h0.x, ua); ffma2(aA0, h0.y, ub);
            ffma2(aA1, h1.x, ua); ffma2(aA1, h1.y, ub);
            ffma2(aA2, h2.x, ua); ffma2(aA2, h2.y, ub);
            ffma2(aA3, h3.x, ua); ffma2(aA3, h3.y, ub);
            ffma2(aB0, h0.x, va); ffma2(aB0, h0.y, vb);
            ffma2(aB1, h1.x, va); ffma2(aB1, h1.y, vb);
            ffma2(aB2, h2.x, va); ffma2(aB2, h2.y, vb);
            ffma2(aB3, h3.x, va); ffma2(aB3, h3.y, vb);
        }
#pragma unroll
        for (int q = 0; q < U1SMJ / 4; ++q) {
            int j0 = U1REGJ + 4 * q;
            ulonglong2 uA = *reinterpret_cast<const ulonglong2*>(&U1sT[tid * U1SMJ + 4 * q]);
            ulonglong2 uB = *reinterpret_cast<const ulonglong2*>(&U1sT[(256 + tid) * U1SMJ + 4 * q]);
            ulonglong2 h0 = *reinterpret_cast<const ulonglong2*>(&hp[0 * H1P + j0]);
            ulonglong2 h1 = *reinterpret_cast<const ulonglong2*>(&hp[1 * H1P + j0]);
            ulonglong2 h2 = *reinterpret_cast<const ulonglong2*>(&hp[2 * H1P + j0]);
            ulonglong2 h3 = *reinterpret_cast<const ulonglong2*>(&hp[3 * H1P + j0]);
            ffma2(aA0, h0.x, uA.x); ffma2(aA0, h0.y, uA.y);
            ffma2(aA1, h1.x, uA.x); ffma2(aA1, h1.y, uA.y);
            ffma2(aA2, h2.x, uA.x); ffma2(aA2, h2.y, uA.y);
            ffma2(aA3, h3.x, uA.x); ffma2(aA3, h3.y, uA.y);
            ffma2(aB0, h0.x, uB.x); ffma2(aB0, h0.y, uB.y);
            ffma2(aB1, h1.x, uB.x); ffma2(aB1, h1.y, uB.y);
            ffma2(aB2, h2.x, uB.x); ffma2(aB2, h2.y, uB.y);
            ffma2(aB3, h3.x, uB.x); ffma2(aB3, h3.y, uB.y);
        }
        float2 sA0 = unpk(aA0), sA1 = unpk(aA1), sA2 = unpk(aA2), sA3 = unpk(aA3);
        float2 sB0 = unpk(aB0), sB1 = unpk(aB1), sB2 = unpk(aB2), sB3 = unpk(aB3);
        float vA0 = sA0.x + sA0.y + zA0;
        float vA1 = sA1.x + sA1.y + zA1;
        float vA2 = sA2.x + sA2.y + zA2;
        float vA3 = sA3.x + sA3.y + zA3;
        float vB0 = sB0.x + sB0.y + zB0;
        float vB1 = sB1.x + sB1.y + zB1;
        float vB2 = sB2.x + sB2.y + zB2;
        float vB3 = sB3.x + sB3.y + zB3;
        if (k == 2) {
            vA0 = fmaxf(vA0, 0.f); vA1 = fmaxf(vA1, 0.f);
            vA2 = fmaxf(vA2, 0.f); vA3 = fmaxf(vA3, 0.f);
            vB0 = fmaxf(vB0, 0.f); vB1 = fmaxf(vB1, 0.f);
            vB2 = fmaxf(vB2, 0.f); vB3 = fmaxf(vB3, 0.f);
        } else {
            vA0 = fsig(vA0); vA1 = fsig(vA1); vA2 = fsig(vA2); vA3 = fsig(vA3);
            vB0 = fsig(vB0); vB1 = fsig(vB1); vB2 = fsig(vB2); vB3 = fsig(vB3);
        }
        quad_transpose(vA0, vA1, vA2, vA3, k);
        quad_transpose(vB0, vB1, vB2, vB3, k);
        {
            cA = fmaf(vA1, cA, vA0 * vA2);
            float h = vA3 * fmaxf(cA, 0.f);
            hT[(1 - (t & 1)) * (4 * H1P) + k * H1P + jA] = h;
            if (j4 < 50) hout[((size_t)t * BATCH + b0 + k) * H1D + jA] = h;
        }
        {
            cB = fmaf(vB1, cB, vB0 * vB2);
            float h = vB3 * fmaxf(cB, 0.f);
            hT[(1 - (t & 1)) * (4 * H1P) + k * H1P + jB] = h;
            if (j4 < 50) hout[((size_t)t * BATCH + b0 + k) * H1D + jB] = h;
        }
        zA0 = nA0; zA1 = nA1; zA2 = nA2; zA3 = nA3;
        zB0 = nB0; zB1 = nB1; zB2 = nB2; zB3 = nB3;
        __syncthreads();
    }
}

// ---------------- layer-2 scan (R13) ----------------------------------------
#define U2REGJ 80
#define U2SMJ  48
#define U2P    52
__global__ __launch_bounds__(256, 1)
void lstm_scan2(const float* __restrict__ zx, const float* __restrict__ U,
                float* __restrict__ h2out)
{
    extern __shared__ __align__(16) float sm2[];
    float* U2sT = sm2;
    float* hT   = sm2 + 512 * U2P;

    const int tid = threadIdx.x;
    const int j  = tid >> 2;
    const int k  = tid & 3;
    const int jA = j, jB = j + 64;
    const int colA = k * H2D + jA;
    const int colB = k * H2D + jB;
    const int b0 = blockIdx.x * 4;

    u64 UpA[U2REGJ / 2], UpB[U2REGJ / 2];
#pragma unroll
    for (int p = 0; p < U2REGJ / 2; ++p) {
        UpA[p] = pack2(U[(2 * p) * G2D + colA], U[(2 * p + 1) * G2D + colA]);
        UpB[p] = pack2(U[(2 * p) * G2D + colB], U[(2 * p + 1) * G2D + colB]);
    }
    for (int idx = tid; idx < U2SMJ * G2D; idx += 256) {
        int r = idx >> 9;
        int cc = idx & 511;
        int jj = cc & 127, kk = cc >> 7;
        int slot = (jj < 64) ? (4 * jj + kk) : (256 + 4 * (jj - 64) + kk);
        U2sT[slot * U2P + r] = U[(size_t)(U2REGJ + r) * G2D + cc];
    }
    for (int i = tid; i < 2 * 4 * H2D; i += 256) hT[i] = 0.f;

    float cA = 0.f, cB = 0.f;
    const float* zbA = zx + colA;
    const float* zbB = zx + colB;
    float zA0 = zbA[((size_t)0 * BATCH + b0 + 0) * G2D];
    float zA1 = zbA[((size_t)0 * BATCH + b0 + 1) * G2D];
    float zA2 = zbA[((size_t)0 * BATCH + b0 + 2) * G2D];
    float zA3 = zbA[((size_t)0 * BATCH + b0 + 3) * G2D];
    float zB0 = zbB[((size_t)0 * BATCH + b0 + 0) * G2D];
    float zB1 = zbB[((size_t)0 * BATCH + b0 + 1) * G2D];
    float zB2 = zbB[((size_t)0 * BATCH + b0 + 2) * G2D];
    float zB3 = zbB[((size_t)0 * BATCH + b0 + 3) * G2D];
    __syncthreads();

#pragma unroll 1
    for (int t = 0; t < T_SEQ; ++t) {
        int tn = (t + 1 < T_SEQ) ? (t + 1) : t;
        float nA0 = zbA[((size_t)tn * BATCH + b0 + 0) * G2D];
        float nA1 = zbA[((size_t)tn * BATCH + b0 + 1) * G2D];
        float nA2 = zbA[((size_t)tn * BATCH + b0 + 2) * G2D];
        float nA3 = zbA[((size_t)tn * BATCH + b0 + 3) * G2D];
        float nB0 = zbB[((size_t)tn * BATCH + b0 + 0) * G2D];
        float nB1 = zbB[((size_t)tn * BATCH + b0 + 1) * G2D];
        float nB2 = zbB[((size_t)tn * BATCH + b0 + 2) * G2D];
        float nB3 = zbB[((size_t)tn * BATCH + b0 + 3) * G2D];

        const float* hp = hT + (t & 1) * (4 * H2D);
        u64 aA0 = 0ull, aA1 = 0ull, aA2 = 0ull, aA3 = 0ull;
        u64 aB0 = 0ull, aB1 = 0ull, aB2 = 0ull, aB3 = 0ull;
#pragma unroll
        for (int p4 = 0; p4 < U2REGJ / 4; ++p4) {
            int j0 = 4 * p4;
            ulonglong2 h0 = *reinterpret_cast<const ulonglong2*>(&hp[0 * H2D + j0]);
            ulonglong2 h1 = *reinterpret_cast<const ulonglong2*>(&hp[1 * H2D + j0]);
            ulonglong2 h2 = *reinterpret_cast<const ulonglong2*>(&hp[2 * H2D + j0]);
            ulonglong2 h3 = *reinterpret_cast<const ulonglong2*>(&hp[3 * H2D + j0]);
            u64 ua = UpA[2 * p4], ub = UpA[2 * p4 + 1];
            u64 va = UpB[2 * p4], vb = UpB[2 * p4 + 1];
            ffma2(aA0, h0.x, ua); ffma2(aA0, h0.y, ub);
            ffma2(aA1, h1.x, ua); ffma2(aA1, h1.y, ub);
            ffma2(aA2, h2.x, ua); ffma2(aA2, h2.y, ub);
            ffma2(aA3, h3.x, ua); ffma2(aA3, h3.y, ub);
            ffma2(aB0, h0.x, va); ffma2(aB0, h0.y, vb);
            ffma2(aB1, h1.x, va); ffma2(aB1, h1.y, vb);
            ffma2(aB2, h2.x, va); ffma2(aB2, h2.y, vb);
            ffma2(aB3, h3.x, va); ffma2(aB3, h3.y, vb);
        }
#pragma unroll
        for (int q = 0; q < U2SMJ / 4; ++q) {
            int j0 = U2REGJ + 4 * q;
            ulonglong2 uA = *reinterpret_cast<const ulonglong2*>(&U2sT[tid * U2P + 4 * q]);
            ulonglong2 uB = *reinterpret_cast<const ulonglong2*>(&U2sT[(256 + tid) * U2P + 4 * q]);
            ulonglong2 h0 = *reinterpret_cast<const ulonglong2*>(&hp[0 * H2D + j0]);
            ulonglong2 h1 = *reinterpret_cast<const ulonglong2*>(&hp[1 * H2D + j0]);
            ulonglong2 h2 = *reinterpret_cast<const ulonglong2*>(&hp[2 * H2D + j0]);
            ulonglong2 h3 = *reinterpret_cast<const ulonglong2*>(&hp[3 * H2D + j0]);
            ffma2(aA0, h0.x, uA.x); ffma2(aA0, h0.y, uA.y);
            ffma2(aA1, h1.x, uA.x); ffma2(aA1, h1.y, uA.y);
            ffma2(aA2, h2.x, uA.x); ffma2(aA2, h2.y, uA.y);
            ffma2(aA3, h3.x, uA.x); ffma2(aA3, h3.y, uA.y);
            ffma2(aB0, h0.x, uB.x); ffma2(aB0, h0.y, uB.y);
            ffma2(aB1, h1.x, uB.x); ffma2(aB1, h1.y, uB.y);
            ffma2(aB2, h2.x, uB.x); ffma2(aB2, h2.y, uB.y);
            ffma2(aB3, h3.x, uB.x); ffma2(aB3, h3.y, uB.y);
        }
        float2 sA0 = unpk(aA0), sA1 = unpk(aA1), sA2 = unpk(aA2), sA3 = unpk(aA3);
        float2 sB0 = unpk(aB0), sB1 = unpk(aB1), sB2 = unpk(aB2), sB3 = unpk(aB3);
        float vA0 = sA0.x + sA0.y + zA0;
        float vA1 = sA1.x + sA1.y + zA1;
        float vA2 = sA2.x + sA2.y + zA2;
        float vA3 = sA3.x + sA3.y + zA3;
        float vB0 = sB0.x + sB0.y + zB0;
        float vB1 = sB1.x + sB1.y + zB1;
        float vB2 = sB2.x + sB2.y + zB2;
        float vB3 = sB3.x + sB3.y + zB3;
        if (k == 2) {
            vA0 = fmaxf(vA0, 0.f); vA1 = fmaxf(vA1, 0.f);
            vA2 = fmaxf(vA2, 0.f); vA3 = fmaxf(vA3, 0.f);
            vB0 = fmaxf(vB0, 0.f); vB1 = fmaxf(vB1, 0.f);
            vB2 = fmaxf(vB2, 0.f); vB3 = fmaxf(vB3, 0.f);
        } else {
            vA0 = fsig(vA0); vA1 = fsig(vA1); vA2 = fsig(vA2); vA3 = fsig(vA3);
            vB0 = fsig(vB0); vB1 = fsig(vB1); vB2 = fsig(vB2); vB3 = fsig(vB3);
        }
        quad_transpose(vA0, vA1, vA2, vA3, k);
        quad_transpose(vB0, vB1, vB2, vB3, k);
        {
            cA = fmaf(vA1, cA, vA0 * vA2);
            float h = vA3 * fmaxf(cA, 0.f);
            hT[(1 - (t & 1)) * (4 * H2D) + k * H2D + jA] = h;
            if (t == T_SEQ - 1) h2out[(b0 + k) * H2D + jA] = h;
        }
        {
            cB = fmaf(vB1, cB, vB0 * vB2);
            float h = vB3 * fmaxf(cB, 0.f);
            hT[(1 - (t & 1)) * (4 * H2D) + k * H2D + jB] = h;
            if (t == T_SEQ - 1) h2out[(b0 + k) * H2D + jB] = h;
        }
        zA0 = nA0; zA1 = nA1; zA2 = nA2; zA3 = nA3;
        zB0 = nB0; zB1 = nB1; zB2 = nB2; zB3 = nB3;
        __syncthreads();
    }
}

// ---------------- dense head + softmax -------------------------------------
__global__ void head_kernel(const float* __restrict__ h2, const float* __restrict__ Wd,
                            const float* __restrict__ bd, float* __restrict__ out)
{
    __shared__ float hsh[H2D];
    const int b = blockIdx.x;
    const int lane = threadIdx.x;
    for (int j = lane; j < H2D; j += 32) hsh[j] = h2[b * H2D + j];
    __syncthreads();

    float acc = 0.f;
    if (lane < NC) {
        acc = bd[lane];
#pragma unroll
        for (int j = 0; j < H2D; ++j) acc = fmaf(hsh[j], Wd[j * NC + lane], acc);
    }
    float v = (lane < NC) ? acc : -FLT_MAX;
#pragma unroll
    for (int off = 16; off > 0; off >>= 1)
        v = fmaxf(v, __shfl_xor_sync(0xffffffffu, v, off));
    float e = (lane < NC) ? expf(acc - v) : 0.f;
    float s = e;
#pragma unroll
    for (int off = 16; off > 0; off >>= 1)
        s += __shfl_xor_sync(0xffffffffu, s, off);
    if (lane < NC) out[b * NC + lane] = e / s;
}

// ---------------- launch ----------------------------------------------------
extern "C" void kernel_launch(void* const* d_in, const int* in_sizes, int n_in,
                              void* d_out, int out_size)
{
    const float* x  = (const float*)d_in[0];
    const float* W1 = (const float*)d_in[1];
    const float* U1 = (const float*)d_in[2];
    const float* b1 = (const float*)d_in[3];
    const float* W2 = (const float*)d_in[4];
    const float* U2 = (const float*)d_in[5];
    const float* b2 = (const float*)d_in[6];
    const float* Wd = (const float*)d_in[7];
    const float* bd = (const float*)d_in[8];
    float* out = (float*)d_out;

    const int gemm_smem  = GSM_ELEMS * 2;                         // 69632
    const int scan1_smem = (512 * U1SMJ + 2 * 4 * H1P) * 4;
    const int scan2_smem = (512 * U2P + 2 * 4 * H2D) * 4;
    cudaFuncSetAttribute(gemm_mma,   cudaFuncAttributeMaxDynamicSharedMemorySize, gemm_smem);
    cudaFuncSetAttribute(lstm_scan1, cudaFuncAttributeMaxDynamicSharedMemorySize, scan1_smem);
    cudaFuncSetAttribute(lstm_scan2, cudaFuncAttributeMaxDynamicSharedMemorySize, scan2_smem);

    float *zx1p, *h1p, *zx2p, *h2p;
    cudaGetSymbolAddress((void**)&zx1p, g_zx1);
    cudaGetSymbolAddress((void**)&h1p,  g_h1);
    cudaGetSymbolAddress((void**)&zx2p, g_zx2);
    cudaGetSymbolAddress((void**)&h2p,  g_h2);
    __nv_bfloat16 *w1h, *w1l, *w2h, *w2l;
    cudaGetSymbolAddress((void**)&w1h, g_w1h);
    cudaGetSymbolAddress((void**)&w1l, g_w1l);
    cudaGetSymbolAddress((void**)&w2h, g_w2h);
    cudaGetSymbolAddress((void**)&w2l, g_w2l);

    const int M = T_SEQ * BATCH;

    conv_weights<<<64, 256>>>(W1, W2);

    gemm_mma<<<M / 64, GT, gemm_smem>>>(x, w1h, w1l, b1, zx1p, G1D, IND, 1);

    lstm_scan1<<<BATCH / 4, 256, scan1_smem>>>(zx1p, U1, h1p);

    gemm_mma<<<M / 64, GT, gemm_smem>>>(h1p, w2h, w2l, b2, zx2p, G2D, H1D, 0);

    lstm_scan2<<<BATCH / 4, 256, scan2_smem>>>(zx2p, U2, h2p);

    head_kernel<<<BATCH, 32>>>(h2p, Wd, bd, out);
}